// round 13
// baseline (speedup 1.0000x reference)
#include <cuda_runtime.h>
#include <cuda_bf16.h>
#include <cstdint>
#include <math.h>

#define SS 2048
#define DM 1024
#define DH 4096
#define MM 8192

// ---------------- device scratch ----------------
__device__ double g_partial[8192];
__device__ float  g_wscale[4];
__device__ unsigned int g_wsum_count;
__device__ __align__(16) __nv_bfloat16 g_xq [(size_t)MM * DM];
__device__ __align__(16) __nv_bfloat16 g_wq1[(size_t)DH * DM];
__device__ __align__(16) __nv_bfloat16 g_wq2[(size_t)DM * DH];
__device__ __align__(16) __nv_bfloat16 g_q2 [(size_t)MM * DH];
__device__ __align__(16) float  g_h  [(size_t)MM * DH];
__device__ float g_rowscale1[MM];
__device__ float g_rowscale2[MM];

// ---------------- helpers ----------------
__device__ __forceinline__ uint32_t pack_bf16(float a, float b) {
    __nv_bfloat162 h = __floats2bfloat162_rn(a, b);
    return *reinterpret_cast<uint32_t*>(&h);
}
__device__ __forceinline__ float block_max(float v, float* sred, int tid, int nthr) {
    #pragma unroll
    for (int o = 16; o > 0; o >>= 1) v = fmaxf(v, __shfl_xor_sync(0xFFFFFFFFu, v, o));
    if ((tid & 31) == 0) sred[tid >> 5] = v;
    __syncthreads();
    int nw = nthr >> 5;
    if (tid < 32) {
        float x = (tid < nw) ? sred[tid] : 0.0f;
        #pragma unroll
        for (int o = 16; o > 0; o >>= 1) x = fmaxf(x, __shfl_xor_sync(0xFFFFFFFFu, x, o));
        if (tid == 0) sred[0] = x;
    }
    __syncthreads();
    float r = sred[0];
    __syncthreads();
    return r;
}
__device__ __forceinline__ float qr(float v, float s, float lo, float hi) {
    return fminf(fmaxf(rintf(v * s), lo), hi);
}

// ---------------- weight mean|w| : partial + last-block final (deterministic) ----------------
__global__ void wsum_all(const float* __restrict__ w1, const float* __restrict__ w2) {
    __shared__ double sd[256];
    __shared__ int slast;
    int blk = blockIdx.x;
    const float* src = (blk < 4096) ? (w1 + (size_t)blk * 1024)
                                    : (w2 + (size_t)(blk - 4096) * 1024);
    int tid = threadIdx.x;
    float4 v = reinterpret_cast<const float4*>(src)[tid];
    double s = ((double)fabsf(v.x) + (double)fabsf(v.y)) +
               ((double)fabsf(v.z) + (double)fabsf(v.w));
    sd[tid] = s; __syncthreads();
    for (int o = 128; o > 0; o >>= 1) { if (tid < o) sd[tid] += sd[tid + o]; __syncthreads(); }
    if (tid == 0) {
        g_partial[blk] = sd[0];
        __threadfence();
        unsigned int old = atomicAdd(&g_wsum_count, 1u);
        slast = (old == 8191u);
    }
    __syncthreads();
    if (slast) {
        // this is the last block: all g_partial entries are visible. Final
        // reduce in fixed order (bit-identical to the old wsum_final).
        for (int a = 0; a < 2; a++) {
            double t = 0.0;
            for (int i = tid; i < 4096; i += 256) t += g_partial[a * 4096 + i];
            sd[tid] = t; __syncthreads();
            for (int o = 128; o > 0; o >>= 1) { if (tid < o) sd[tid] += sd[tid + o]; __syncthreads(); }
            if (tid == 0) {
                float mean = (float)(sd[0] / (4096.0 * 1024.0));
                float mc = fmaxf(mean, 1e-5f);
                g_wscale[a]     = mc;
                g_wscale[2 + a] = 1.0f / mc;
            }
            __syncthreads();
        }
        if (tid == 0) g_wsum_count = 0;   // reset: every launch does identical work
    }
}

// ---------------- fused quantization: w1 | w2 | x -> bf16 ----------------
__global__ void __launch_bounds__(256) quant_all(const float* __restrict__ w1,
                                                 const float* __restrict__ w2,
                                                 const float* __restrict__ x) {
    __shared__ float sred[32];
    int blk = blockIdx.x, tid = threadIdx.x;
    if (blk < 8192) {
        int which = (blk >= 4096);
        const float* src = which ? w2 : w1;
        __nv_bfloat16* dst = which ? g_wq2 : g_wq1;
        size_t idx = (size_t)(blk & 4095) * 1024 + (size_t)tid * 4;
        float sw = g_wscale[2 + which];
        float4 v = *reinterpret_cast<const float4*>(src + idx);
        uint2 p = make_uint2(pack_bf16(qr(v.x, sw, -1.f, 1.f), qr(v.y, sw, -1.f, 1.f)),
                             pack_bf16(qr(v.z, sw, -1.f, 1.f), qr(v.w, sw, -1.f, 1.f)));
        *reinterpret_cast<uint2*>(dst + idx) = p;
    } else {
        int m = blk - 8192;
        float4 v = reinterpret_cast<const float4*>(x + (size_t)m * DM)[tid];
        float amax = fmaxf(fmaxf(fabsf(v.x), fabsf(v.y)), fmaxf(fabsf(v.z), fabsf(v.w)));
        amax = block_max(amax, sred, tid, 256);
        float s = 127.0f / fmaxf(amax, 1e-5f);
        uint2 p = make_uint2(pack_bf16(qr(v.x, s, -128.f, 127.f), qr(v.y, s, -128.f, 127.f)),
                             pack_bf16(qr(v.z, s, -128.f, 127.f), qr(v.w, s, -128.f, 127.f)));
        *reinterpret_cast<uint2*>(g_xq + (size_t)m * DM + (size_t)tid * 4) = p;
        if (tid == 0) g_rowscale1[m] = 1.0f / s;
    }
}

// ---------------- conv3 + SiLU + per-token quant, 4 tokens/block ----------------
__global__ void __launch_bounds__(512) conv_silu_quant4(const float* __restrict__ cw,
                                                        const float* __restrict__ cb) {
    __shared__ float sred4[16][4];
    __shared__ float s2s[4];
    int g0 = blockIdx.x * 4;              // first token of group (never crosses batch)
    int tid = threadIdx.x;
    int c0 = tid * 8;
    int spos0 = g0 & (SS - 1);

    float warr[24];
    #pragma unroll
    for (int i = 0; i < 6; i++) {
        float4 v = *reinterpret_cast<const float4*>(cw + (size_t)c0 * 3 + i * 4);
        warr[i*4+0]=v.x; warr[i*4+1]=v.y; warr[i*4+2]=v.z; warr[i*4+3]=v.w;
    }
    float bv[8];
    #pragma unroll
    for (int i = 0; i < 2; i++) {
        float4 v = *reinterpret_cast<const float4*>(cb + c0 + i * 4);
        bv[i*4+0]=v.x; bv[i*4+1]=v.y; bv[i*4+2]=v.z; bv[i*4+3]=v.w;
    }

    const float* hbase = g_h + (size_t)g0 * DH + c0;

    float w0r[8], w1r[8], w2r[8];
    #pragma unroll
    for (int i = 0; i < 2; i++) {
        float4 vm = (spos0 > 0) ? *reinterpret_cast<const float4*>(hbase - DH + i * 4)
                                : make_float4(0.f,0.f,0.f,0.f);
        w0r[i*4+0]=vm.x; w0r[i*4+1]=vm.y; w0r[i*4+2]=vm.z; w0r[i*4+3]=vm.w;
        float4 vc = *reinterpret_cast<const float4*>(hbase + i * 4);
        w1r[i*4+0]=vc.x; w1r[i*4+1]=vc.y; w1r[i*4+2]=vc.z; w1r[i*4+3]=vc.w;
    }

    float y[4][8];
    float amax[4];
    #pragma unroll
    for (int t = 0; t < 4; t++) {
        bool valid = !(t == 3 && spos0 == SS - 4);
        #pragma unroll
        for (int i = 0; i < 2; i++) {
            float4 vp = valid ? *reinterpret_cast<const float4*>(hbase + (size_t)(t + 1) * DH + i * 4)
                              : make_float4(0.f,0.f,0.f,0.f);
            w2r[i*4+0]=vp.x; w2r[i*4+1]=vp.y; w2r[i*4+2]=vp.z; w2r[i*4+3]=vp.w;
        }
        float am = 0.0f;
        #pragma unroll
        for (int j = 0; j < 8; j++) {
            float v = bv[j];
            v = fmaf(warr[3*j+0], w0r[j], v);
            v = fmaf(warr[3*j+1], w1r[j], v);
            v = fmaf(warr[3*j+2], w2r[j], v);
            v = v / (1.0f + expf(-v));        // SiLU
            y[t][j] = v;
            am = fmaxf(am, fabsf(v));
        }
        amax[t] = am;
        #pragma unroll
        for (int j = 0; j < 8; j++) { w0r[j] = w1r[j]; w1r[j] = w2r[j]; }
    }

    #pragma unroll
    for (int t = 0; t < 4; t++) {
        float v = amax[t];
        #pragma unroll
        for (int o = 16; o > 0; o >>= 1) v = fmaxf(v, __shfl_xor_sync(0xFFFFFFFFu, v, o));
        if ((tid & 31) == 0) sred4[tid >> 5][t] = v;
    }
    __syncthreads();
    if (tid < 128) {
        int w = tid >> 5, lane = tid & 31;
        float v = (lane < 16) ? sred4[lane][w] : 0.0f;
        #pragma unroll
        for (int o = 8; o > 0; o >>= 1) v = fmaxf(v, __shfl_xor_sync(0xFFFFFFFFu, v, o));
        if (lane == 0) {
            float s2 = 127.0f / fmaxf(v, 1e-5f);
            s2s[w] = s2;
            g_rowscale2[g0 + w] = 1.0f / s2;
        }
    }
    __syncthreads();

    #pragma unroll
    for (int t = 0; t < 4; t++) {
        float s2 = s2s[t];
        uint4 p;
        p.x = pack_bf16(qr(y[t][0], s2, -128.f, 127.f), qr(y[t][1], s2, -128.f, 127.f));
        p.y = pack_bf16(qr(y[t][2], s2, -128.f, 127.f), qr(y[t][3], s2, -128.f, 127.f));
        p.z = pack_bf16(qr(y[t][4], s2, -128.f, 127.f), qr(y[t][5], s2, -128.f, 127.f));
        p.w = pack_bf16(qr(y[t][6], s2, -128.f, 127.f), qr(y[t][7], s2, -128.f, 127.f));
        *reinterpret_cast<uint4*>(g_q2 + (size_t)(g0 + t) * DH + c0) = p;
    }
}

// ====== bf16 HMMA GEMM: 128x128 block, 128 threads, 64x64 warp tiles ======
// 2 CTAs/SM, 3-stage cp.async, ks-level fragment double-buffering,
// split A/B prefetch interleaved with MMA to reduce LSU burst contention.
#define BM 128
#define BN 128
#define BK 64                      // 64 bf16 = 128 bytes per smem row
#define STAGES 3
#define TILE_BYTES (128 * 128)     // 16 KB per operand tile
#define STAGE_BYTES (2 * TILE_BYTES)
#define GSMEM_TOTAL (STAGES * STAGE_BYTES)   // 96 KB

__device__ __forceinline__ void cp_async16(uint32_t saddr, const void* g) {
    asm volatile("cp.async.cg.shared.global [%0], [%1], 16;\n" :: "r"(saddr), "l"(g));
}
__device__ __forceinline__ void cp_commit() { asm volatile("cp.async.commit_group;\n"); }
__device__ __forceinline__ void cp_wait1()  { asm volatile("cp.async.wait_group 1;\n"); }

__device__ __forceinline__ void ldm_x4(uint32_t* r, uint32_t saddr) {
    asm volatile("ldmatrix.sync.aligned.m8n8.x4.shared.b16 {%0,%1,%2,%3}, [%4];\n"
        : "=r"(r[0]), "=r"(r[1]), "=r"(r[2]), "=r"(r[3]) : "r"(saddr));
}
__device__ __forceinline__ void mma16816(float* d, const uint32_t* a, const uint32_t* b) {
    asm volatile(
        "mma.sync.aligned.m16n8k16.row.col.f32.bf16.bf16.f32 "
        "{%0,%1,%2,%3},{%4,%5,%6,%7},{%8,%9},{%0,%1,%2,%3};\n"
        : "+f"(d[0]), "+f"(d[1]), "+f"(d[2]), "+f"(d[3])
        : "r"(a[0]), "r"(a[1]), "r"(a[2]), "r"(a[3]), "r"(b[0]), "r"(b[1]));
}

// load one 128x64 operand tile with 128 threads (8 cp each)
// 16B-chunk swizzle: phys = ch ^ (row&7)  -> conflict-free ldmatrix + stores
template <int KK>
__device__ __forceinline__ void load_tile_half(uint32_t sT, const __nv_bfloat16* G,
                                               int kElem, int tid) {
    #pragma unroll
    for (int i = 0; i < 8; i++) {
        int c = tid + i * 128;
        int row = c >> 3, ch = c & 7;
        int phys = ch ^ (row & 7);
        cp_async16(sT + row * 128 + phys * 16,
                   (const char*)(G + (size_t)row * KK + kElem) + ch * 16);
    }
}

// WHICH=0: A=g_xq B=g_wq1 C=g_h   WHICH=1: A=g_q2 B=g_wq2 C=out
template <int WHICH, int NN, int KK>
__global__ void __launch_bounds__(128, 2) gemm_bf16(float* __restrict__ Cout) {
    extern __shared__ __align__(16) char smem[];
    uint32_t s0 = (uint32_t)__cvta_generic_to_shared(smem);

    const __nv_bfloat16* A  = WHICH ? g_q2 : g_xq;
    const __nv_bfloat16* B  = WHICH ? g_wq2 : g_wq1;
    float*               C  = WHICH ? Cout : g_h;
    const float*         rs = WHICH ? g_rowscale2 : g_rowscale1;

    const int tid = threadIdx.x, lane = tid & 31, wid = tid >> 5;
    const int wm = (wid >> 1) * 64, wn = (wid & 1) * 64;   // 2x2 warp grid, 64x64 tiles
    const int m0 = blockIdx.y * BM, n0 = blockIdx.x * BN;

    const __nv_bfloat16* Ag = A + (size_t)m0 * KK;
    const __nv_bfloat16* Bg = B + (size_t)n0 * KK;

    // ldmatrix per-lane base addressing (proven R7 pattern)
    const int rA = wm + (lane & 15);           // + im*16
    const int hiA = lane >> 4;                 // k-half select
    const int xA = rA & 7;
    const int gB = lane >> 3, lrB = lane & 7;
    const int rB = wn + ((gB & 2) << 2) + lrB; // + jp*16
    const int hiB = gB & 1;
    const int xB = rB & 7;

    float acc[4][8][4];
    #pragma unroll
    for (int im = 0; im < 4; im++)
        #pragma unroll
        for (int jn = 0; jn < 8; jn++)
            #pragma unroll
            for (int q = 0; q < 4; q++) acc[im][jn][q] = 0.0f;

    uint32_t af[2][4][4], bf[2][4][4];   // double-buffered fragments

    constexpr int KT = KK / BK;
    #pragma unroll
    for (int p = 0; p < STAGES - 1; p++) {
        load_tile_half<KK>(s0 + p * STAGE_BYTES, Ag, p * BK, tid);
        load_tile_half<KK>(s0 + p * STAGE_BYTES + TILE_BYTES, Bg, p * BK, tid);
        cp_commit();
    }

    for (int kt = 0; kt < KT; kt++) {
        cp_wait1();                 // stage kt resident
        __syncthreads();            // all warps done with buffer about to be refilled

        const uint32_t sA = s0 + (uint32_t)(kt % STAGES) * STAGE_BYTES;
        const uint32_t sB = sA + TILE_BYTES;
        const uint32_t aL = sA + (uint32_t)rA * 128;
        const uint32_t bL = sB + (uint32_t)rB * 128;

        const int nk = kt + STAGES - 1;
        const bool doload = (nk < KT);
        const int pb = nk % STAGES;
        const uint32_t pA = s0 + (uint32_t)pb * STAGE_BYTES;
        const uint32_t pB = pA + TILE_BYTES;

        // ks=0 fragments first (gets LDSM started before any cp.async burst)
        {
            const uint32_t ofA = (uint32_t)((hiA ^ xA) << 4);
            #pragma unroll
            for (int im = 0; im < 4; im++)
                ldm_x4(af[0][im], aL + (uint32_t)(im * 16 * 128) + ofA);
            const uint32_t ofB = (uint32_t)((hiB ^ xB) << 4);
            #pragma unroll
            for (int jp = 0; jp < 4; jp++)
                ldm_x4(bf[0][jp], bL + (uint32_t)(jp * 16 * 128) + ofB);
        }

        // A-half of the kt+2 prefetch (B-half goes after ks0's MMAs)
        if (doload) load_tile_half<KK>(pA, Ag, nk * BK, tid);

        #pragma unroll
        for (int ks = 0; ks < 4; ks++) {
            const int cur = ks & 1;
            if (ks < 3) {           // prefetch next k-chunk fragments
                const int nxt = cur ^ 1;
                const uint32_t ofA = (uint32_t)((((ks + 1) * 2 + hiA) ^ xA) << 4);
                #pragma unroll
                for (int im = 0; im < 4; im++)
                    ldm_x4(af[nxt][im], aL + (uint32_t)(im * 16 * 128) + ofA);
                const uint32_t ofB = (uint32_t)((((ks + 1) * 2 + hiB) ^ xB) << 4);
                #pragma unroll
                for (int jp = 0; jp < 4; jp++)
                    ldm_x4(bf[nxt][jp], bL + (uint32_t)(jp * 16 * 128) + ofB);
            }
            #pragma unroll
            for (int im = 0; im < 4; im++)
                #pragma unroll
                for (int jn = 0; jn < 8; jn++)
                    mma16816(acc[im][jn], af[cur][im], &bf[cur][jn >> 1][(jn & 1) * 2]);
            if (ks == 0) {          // B-half of prefetch + single commit per tile
                if (doload) load_tile_half<KK>(pB, Bg, nk * BK, tid);
                cp_commit();
            }
        }
    }

    const float ws = g_wscale[WHICH];
    const int g = lane >> 2, t = lane & 3;
    #pragma unroll
    for (int im = 0; im < 4; im++) {
        int r0 = m0 + wm + im * 16 + g;
        float rs0 = rs[r0] * ws;
        float rs1 = rs[r0 + 8] * ws;
        #pragma unroll
        for (int jn = 0; jn < 8; jn++) {
            int cc = n0 + wn + jn * 8 + t * 2;
            float2 v0 = make_float2(acc[im][jn][0] * rs0, acc[im][jn][1] * rs0);
            float2 v1 = make_float2(acc[im][jn][2] * rs1, acc[im][jn][3] * rs1);
            *reinterpret_cast<float2*>(&C[(size_t)r0 * NN + cc]) = v0;
            *reinterpret_cast<float2*>(&C[(size_t)(r0 + 8) * NN + cc]) = v1;
        }
    }
}

// ---------------- launch ----------------
extern "C" void kernel_launch(void* const* d_in, const int* in_sizes, int n_in,
                              void* d_out, int out_size) {
    const float* x  = (const float*)d_in[0];
    const float* w1 = (const float*)d_in[1];
    const float* cw = (const float*)d_in[2];
    const float* cb = (const float*)d_in[3];
    const float* w2 = (const float*)d_in[4];
    float* out = (float*)d_out;
    (void)in_sizes; (void)n_in; (void)out_size;

    static int inited = 0;
    if (!inited) {
        cudaFuncSetAttribute(gemm_bf16<0, DH, DM>, cudaFuncAttributeMaxDynamicSharedMemorySize, GSMEM_TOTAL);
        cudaFuncSetAttribute(gemm_bf16<1, DM, DH>, cudaFuncAttributeMaxDynamicSharedMemorySize, GSMEM_TOTAL);
        inited = 1;
    }

    wsum_all<<<8192, 256>>>(w1, w2);                                            // 1
    quant_all<<<16384, 256>>>(w1, w2, x);                                       // 2
    gemm_bf16<0, DH, DM><<<dim3(DH / BN, MM / BM), 128, GSMEM_TOTAL>>>(nullptr);// 3
    conv_silu_quant4<<<MM / 4, 512>>>(cw, cb);                                  // 4
    gemm_bf16<1, DM, DH><<<dim3(DM / BN, MM / BM), 128, GSMEM_TOTAL>>>(out);    // 5
}

// round 14
// speedup vs baseline: 1.0150x; 1.0150x over previous
#include <cuda_runtime.h>
#include <cuda_bf16.h>
#include <cstdint>
#include <math.h>

#define SS 2048
#define DM 1024
#define DH 4096
#define MM 8192

// ---------------- device scratch ----------------
__device__ double g_partial[8192];
__device__ float  g_wscale[4];
__device__ unsigned int g_wsum_count;
__device__ __align__(16) __nv_bfloat16 g_xq [(size_t)MM * DM];
__device__ __align__(16) __nv_bfloat16 g_wq1[(size_t)DH * DM];
__device__ __align__(16) __nv_bfloat16 g_wq2[(size_t)DM * DH];
__device__ __align__(16) __nv_bfloat16 g_q2 [(size_t)MM * DH];
__device__ __align__(16) float  g_h  [(size_t)MM * DH];
__device__ float g_rowscale1[MM];
__device__ float g_rowscale2[MM];

// ---------------- helpers ----------------
__device__ __forceinline__ uint32_t pack_bf16(float a, float b) {
    __nv_bfloat162 h = __floats2bfloat162_rn(a, b);
    return *reinterpret_cast<uint32_t*>(&h);
}
__device__ __forceinline__ float block_max(float v, float* sred, int tid, int nthr) {
    #pragma unroll
    for (int o = 16; o > 0; o >>= 1) v = fmaxf(v, __shfl_xor_sync(0xFFFFFFFFu, v, o));
    if ((tid & 31) == 0) sred[tid >> 5] = v;
    __syncthreads();
    int nw = nthr >> 5;
    if (tid < 32) {
        float x = (tid < nw) ? sred[tid] : 0.0f;
        #pragma unroll
        for (int o = 16; o > 0; o >>= 1) x = fmaxf(x, __shfl_xor_sync(0xFFFFFFFFu, x, o));
        if (tid == 0) sred[0] = x;
    }
    __syncthreads();
    float r = sred[0];
    __syncthreads();
    return r;
}
__device__ __forceinline__ float qr(float v, float s, float lo, float hi) {
    return fminf(fmaxf(rintf(v * s), lo), hi);
}

// ---------------- weight mean|w| : partial + last-block final (deterministic) ----------------
__global__ void wsum_all(const float* __restrict__ w1, const float* __restrict__ w2) {
    __shared__ double sd[256];
    __shared__ int slast;
    int blk = blockIdx.x;
    const float* src = (blk < 4096) ? (w1 + (size_t)blk * 1024)
                                    : (w2 + (size_t)(blk - 4096) * 1024);
    int tid = threadIdx.x;
    float4 v = reinterpret_cast<const float4*>(src)[tid];
    double s = ((double)fabsf(v.x) + (double)fabsf(v.y)) +
               ((double)fabsf(v.z) + (double)fabsf(v.w));
    sd[tid] = s; __syncthreads();
    for (int o = 128; o > 0; o >>= 1) { if (tid < o) sd[tid] += sd[tid + o]; __syncthreads(); }
    if (tid == 0) {
        g_partial[blk] = sd[0];
        __threadfence();
        unsigned int old = atomicAdd(&g_wsum_count, 1u);
        slast = (old == 8191u);
    }
    __syncthreads();
    if (slast) {
        for (int a = 0; a < 2; a++) {
            double t = 0.0;
            for (int i = tid; i < 4096; i += 256) t += g_partial[a * 4096 + i];
            sd[tid] = t; __syncthreads();
            for (int o = 128; o > 0; o >>= 1) { if (tid < o) sd[tid] += sd[tid + o]; __syncthreads(); }
            if (tid == 0) {
                float mean = (float)(sd[0] / (4096.0 * 1024.0));
                float mc = fmaxf(mean, 1e-5f);
                g_wscale[a]     = mc;
                g_wscale[2 + a] = 1.0f / mc;
            }
            __syncthreads();
        }
        if (tid == 0) g_wsum_count = 0;   // reset: every launch does identical work
    }
}

// ---------------- fused quantization: w1 | w2 | x -> bf16 ----------------
__global__ void __launch_bounds__(256) quant_all(const float* __restrict__ w1,
                                                 const float* __restrict__ w2,
                                                 const float* __restrict__ x) {
    __shared__ float sred[32];
    int blk = blockIdx.x, tid = threadIdx.x;
    if (blk < 8192) {
        int which = (blk >= 4096);
        const float* src = which ? w2 : w1;
        __nv_bfloat16* dst = which ? g_wq2 : g_wq1;
        size_t idx = (size_t)(blk & 4095) * 1024 + (size_t)tid * 4;
        float sw = g_wscale[2 + which];
        float4 v = *reinterpret_cast<const float4*>(src + idx);
        uint2 p = make_uint2(pack_bf16(qr(v.x, sw, -1.f, 1.f), qr(v.y, sw, -1.f, 1.f)),
                             pack_bf16(qr(v.z, sw, -1.f, 1.f), qr(v.w, sw, -1.f, 1.f)));
        *reinterpret_cast<uint2*>(dst + idx) = p;
    } else {
        int m = blk - 8192;
        float4 v = reinterpret_cast<const float4*>(x + (size_t)m * DM)[tid];
        float amax = fmaxf(fmaxf(fabsf(v.x), fabsf(v.y)), fmaxf(fabsf(v.z), fabsf(v.w)));
        amax = block_max(amax, sred, tid, 256);
        float s = 127.0f / fmaxf(amax, 1e-5f);
        uint2 p = make_uint2(pack_bf16(qr(v.x, s, -128.f, 127.f), qr(v.y, s, -128.f, 127.f)),
                             pack_bf16(qr(v.z, s, -128.f, 127.f), qr(v.w, s, -128.f, 127.f)));
        *reinterpret_cast<uint2*>(g_xq + (size_t)m * DM + (size_t)tid * 4) = p;
        if (tid == 0) g_rowscale1[m] = 1.0f / s;
    }
}

// ---------------- conv3 + SiLU + per-token quant, 4 tokens/block ----------------
__global__ void __launch_bounds__(512) conv_silu_quant4(const float* __restrict__ cw,
                                                        const float* __restrict__ cb) {
    __shared__ float sred4[16][4];
    __shared__ float s2s[4];
    int g0 = blockIdx.x * 4;              // first token of group (never crosses batch)
    int tid = threadIdx.x;
    int c0 = tid * 8;
    int spos0 = g0 & (SS - 1);

    float warr[24];
    #pragma unroll
    for (int i = 0; i < 6; i++) {
        float4 v = *reinterpret_cast<const float4*>(cw + (size_t)c0 * 3 + i * 4);
        warr[i*4+0]=v.x; warr[i*4+1]=v.y; warr[i*4+2]=v.z; warr[i*4+3]=v.w;
    }
    float bv[8];
    #pragma unroll
    for (int i = 0; i < 2; i++) {
        float4 v = *reinterpret_cast<const float4*>(cb + c0 + i * 4);
        bv[i*4+0]=v.x; bv[i*4+1]=v.y; bv[i*4+2]=v.z; bv[i*4+3]=v.w;
    }

    const float* hbase = g_h + (size_t)g0 * DH + c0;

    float w0r[8], w1r[8], w2r[8];
    #pragma unroll
    for (int i = 0; i < 2; i++) {
        float4 vm = (spos0 > 0) ? *reinterpret_cast<const float4*>(hbase - DH + i * 4)
                                : make_float4(0.f,0.f,0.f,0.f);
        w0r[i*4+0]=vm.x; w0r[i*4+1]=vm.y; w0r[i*4+2]=vm.z; w0r[i*4+3]=vm.w;
        float4 vc = *reinterpret_cast<const float4*>(hbase + i * 4);
        w1r[i*4+0]=vc.x; w1r[i*4+1]=vc.y; w1r[i*4+2]=vc.z; w1r[i*4+3]=vc.w;
    }

    float y[4][8];
    float amax[4];
    #pragma unroll
    for (int t = 0; t < 4; t++) {
        bool valid = !(t == 3 && spos0 == SS - 4);
        #pragma unroll
        for (int i = 0; i < 2; i++) {
            float4 vp = valid ? *reinterpret_cast<const float4*>(hbase + (size_t)(t + 1) * DH + i * 4)
                              : make_float4(0.f,0.f,0.f,0.f);
            w2r[i*4+0]=vp.x; w2r[i*4+1]=vp.y; w2r[i*4+2]=vp.z; w2r[i*4+3]=vp.w;
        }
        float am = 0.0f;
        #pragma unroll
        for (int j = 0; j < 8; j++) {
            float v = bv[j];
            v = fmaf(warr[3*j+0], w0r[j], v);
            v = fmaf(warr[3*j+1], w1r[j], v);
            v = fmaf(warr[3*j+2], w2r[j], v);
            v = v / (1.0f + __expf(-v));      // SiLU (MUFU-based exp)
            y[t][j] = v;
            am = fmaxf(am, fabsf(v));
        }
        amax[t] = am;
        #pragma unroll
        for (int j = 0; j < 8; j++) { w0r[j] = w1r[j]; w1r[j] = w2r[j]; }
    }

    #pragma unroll
    for (int t = 0; t < 4; t++) {
        float v = amax[t];
        #pragma unroll
        for (int o = 16; o > 0; o >>= 1) v = fmaxf(v, __shfl_xor_sync(0xFFFFFFFFu, v, o));
        if ((tid & 31) == 0) sred4[tid >> 5][t] = v;
    }
    __syncthreads();
    if (tid < 128) {
        int w = tid >> 5, lane = tid & 31;
        float v = (lane < 16) ? sred4[lane][w] : 0.0f;
        #pragma unroll
        for (int o = 8; o > 0; o >>= 1) v = fmaxf(v, __shfl_xor_sync(0xFFFFFFFFu, v, o));
        if (lane == 0) {
            float s2 = 127.0f / fmaxf(v, 1e-5f);
            s2s[w] = s2;
            g_rowscale2[g0 + w] = 1.0f / s2;
        }
    }
    __syncthreads();

    #pragma unroll
    for (int t = 0; t < 4; t++) {
        float s2 = s2s[t];
        uint4 p;
        p.x = pack_bf16(qr(y[t][0], s2, -128.f, 127.f), qr(y[t][1], s2, -128.f, 127.f));
        p.y = pack_bf16(qr(y[t][2], s2, -128.f, 127.f), qr(y[t][3], s2, -128.f, 127.f));
        p.z = pack_bf16(qr(y[t][4], s2, -128.f, 127.f), qr(y[t][5], s2, -128.f, 127.f));
        p.w = pack_bf16(qr(y[t][6], s2, -128.f, 127.f), qr(y[t][7], s2, -128.f, 127.f));
        *reinterpret_cast<uint4*>(g_q2 + (size_t)(g0 + t) * DH + c0) = p;
    }
}

// ====== bf16 HMMA GEMM: 128x128 block, 128 threads, 64x64 warp tiles ======
// 2 CTAs/SM, 3-stage cp.async, ks-level fragment double-buffering.
// (R12 configuration — known good at 485.4us; do not touch.)
#define BM 128
#define BN 128
#define BK 64                      // 64 bf16 = 128 bytes per smem row
#define STAGES 3
#define TILE_BYTES (128 * 128)     // 16 KB per operand tile
#define STAGE_BYTES (2 * TILE_BYTES)
#define GSMEM_TOTAL (STAGES * STAGE_BYTES)   // 96 KB

__device__ __forceinline__ void cp_async16(uint32_t saddr, const void* g) {
    asm volatile("cp.async.cg.shared.global [%0], [%1], 16;\n" :: "r"(saddr), "l"(g));
}
__device__ __forceinline__ void cp_commit() { asm volatile("cp.async.commit_group;\n"); }
__device__ __forceinline__ void cp_wait1()  { asm volatile("cp.async.wait_group 1;\n"); }

__device__ __forceinline__ void ldm_x4(uint32_t* r, uint32_t saddr) {
    asm volatile("ldmatrix.sync.aligned.m8n8.x4.shared.b16 {%0,%1,%2,%3}, [%4];\n"
        : "=r"(r[0]), "=r"(r[1]), "=r"(r[2]), "=r"(r[3]) : "r"(saddr));
}
__device__ __forceinline__ void mma16816(float* d, const uint32_t* a, const uint32_t* b) {
    asm volatile(
        "mma.sync.aligned.m16n8k16.row.col.f32.bf16.bf16.f32 "
        "{%0,%1,%2,%3},{%4,%5,%6,%7},{%8,%9},{%0,%1,%2,%3};\n"
        : "+f"(d[0]), "+f"(d[1]), "+f"(d[2]), "+f"(d[3])
        : "r"(a[0]), "r"(a[1]), "r"(a[2]), "r"(a[3]), "r"(b[0]), "r"(b[1]));
}

// load one 128x64 A tile + 128x64 B tile with 128 threads (16 cp each)
// 16B-chunk swizzle: phys = ch ^ (row&7)  -> conflict-free ldmatrix + stores
template <int KK>
__device__ __forceinline__ void load_stage(uint32_t sA, uint32_t sB,
                                           const __nv_bfloat16* Ag, const __nv_bfloat16* Bg,
                                           int kElem, int tid) {
    #pragma unroll
    for (int i = 0; i < 8; i++) {          // A: 1024 chunks
        int c = tid + i * 128;
        int row = c >> 3, ch = c & 7;
        int phys = ch ^ (row & 7);
        cp_async16(sA + row * 128 + phys * 16,
                   (const char*)(Ag + (size_t)row * KK + kElem) + ch * 16);
    }
    #pragma unroll
    for (int i = 0; i < 8; i++) {          // B: 1024 chunks
        int c = tid + i * 128;
        int row = c >> 3, ch = c & 7;
        int phys = ch ^ (row & 7);
        cp_async16(sB + row * 128 + phys * 16,
                   (const char*)(Bg + (size_t)row * KK + kElem) + ch * 16);
    }
    cp_commit();
}

// WHICH=0: A=g_xq B=g_wq1 C=g_h   WHICH=1: A=g_q2 B=g_wq2 C=out
template <int WHICH, int NN, int KK>
__global__ void __launch_bounds__(128, 2) gemm_bf16(float* __restrict__ Cout) {
    extern __shared__ __align__(16) char smem[];
    uint32_t s0 = (uint32_t)__cvta_generic_to_shared(smem);

    const __nv_bfloat16* A  = WHICH ? g_q2 : g_xq;
    const __nv_bfloat16* B  = WHICH ? g_wq2 : g_wq1;
    float*               C  = WHICH ? Cout : g_h;
    const float*         rs = WHICH ? g_rowscale2 : g_rowscale1;

    const int tid = threadIdx.x, lane = tid & 31, wid = tid >> 5;
    const int wm = (wid >> 1) * 64, wn = (wid & 1) * 64;   // 2x2 warp grid, 64x64 tiles
    const int m0 = blockIdx.y * BM, n0 = blockIdx.x * BN;

    const __nv_bfloat16* Ag = A + (size_t)m0 * KK;
    const __nv_bfloat16* Bg = B + (size_t)n0 * KK;

    // ldmatrix per-lane base addressing (proven R7 pattern)
    const int rA = wm + (lane & 15);           // + im*16
    const int hiA = lane >> 4;                 // k-half select
    const int xA = rA & 7;
    const int gB = lane >> 3, lrB = lane & 7;
    const int rB = wn + ((gB & 2) << 2) + lrB; // + jp*16
    const int hiB = gB & 1;
    const int xB = rB & 7;

    float acc[4][8][4];
    #pragma unroll
    for (int im = 0; im < 4; im++)
        #pragma unroll
        for (int jn = 0; jn < 8; jn++)
            #pragma unroll
            for (int q = 0; q < 4; q++) acc[im][jn][q] = 0.0f;

    uint32_t af[2][4][4], bf[2][4][4];   // double-buffered fragments

    constexpr int KT = KK / BK;
    #pragma unroll
    for (int p = 0; p < STAGES - 1; p++)
        load_stage<KK>(s0 + p * STAGE_BYTES, s0 + p * STAGE_BYTES + TILE_BYTES,
                       Ag, Bg, p * BK, tid);

    for (int kt = 0; kt < KT; kt++) {
        cp_wait1();                 // stage kt resident
        __syncthreads();            // all warps done with buffer about to be refilled

        const uint32_t sA = s0 + (uint32_t)(kt % STAGES) * STAGE_BYTES;
        const uint32_t sB = sA + TILE_BYTES;
        const uint32_t aL = sA + (uint32_t)rA * 128;
        const uint32_t bL = sB + (uint32_t)rB * 128;

        // ks=0 fragments first (gets LDSM started before the cp.async burst)
        {
            const uint32_t ofA = (uint32_t)((hiA ^ xA) << 4);
            #pragma unroll
            for (int im = 0; im < 4; im++)
                ldm_x4(af[0][im], aL + (uint32_t)(im * 16 * 128) + ofA);
            const uint32_t ofB = (uint32_t)((hiB ^ xB) << 4);
            #pragma unroll
            for (int jp = 0; jp < 4; jp++)
                ldm_x4(bf[0][jp], bL + (uint32_t)(jp * 16 * 128) + ofB);
        }

        // prefetch stage kt+2
        {
            int nk = kt + STAGES - 1;
            if (nk < KT) {
                int pb = nk % STAGES;
                load_stage<KK>(s0 + pb * STAGE_BYTES, s0 + pb * STAGE_BYTES + TILE_BYTES,
                               Ag, Bg, nk * BK, tid);
            } else {
                cp_commit();        // keep group accounting uniform
            }
        }

        #pragma unroll
        for (int ks = 0; ks < 4; ks++) {
            const int cur = ks & 1;
            if (ks < 3) {           // prefetch next k-chunk fragments
                const int nxt = cur ^ 1;
                const uint32_t ofA = (uint32_t)((((ks + 1) * 2 + hiA) ^ xA) << 4);
                #pragma unroll
                for (int im = 0; im < 4; im++)
                    ldm_x4(af[nxt][im], aL + (uint32_t)(im * 16 * 128) + ofA);
                const uint32_t ofB = (uint32_t)((((ks + 1) * 2 + hiB) ^ xB) << 4);
                #pragma unroll
                for (int jp = 0; jp < 4; jp++)
                    ldm_x4(bf[nxt][jp], bL + (uint32_t)(jp * 16 * 128) + ofB);
            }
            #pragma unroll
            for (int im = 0; im < 4; im++)
                #pragma unroll
                for (int jn = 0; jn < 8; jn++)
                    mma16816(acc[im][jn], af[cur][im], &bf[cur][jn >> 1][(jn & 1) * 2]);
        }
    }

    const float ws = g_wscale[WHICH];
    const int g = lane >> 2, t = lane & 3;
    #pragma unroll
    for (int im = 0; im < 4; im++) {
        int r0 = m0 + wm + im * 16 + g;
        float rs0 = rs[r0] * ws;
        float rs1 = rs[r0 + 8] * ws;
        #pragma unroll
        for (int jn = 0; jn < 8; jn++) {
            int cc = n0 + wn + jn * 8 + t * 2;
            float2 v0 = make_float2(acc[im][jn][0] * rs0, acc[im][jn][1] * rs0);
            float2 v1 = make_float2(acc[im][jn][2] * rs1, acc[im][jn][3] * rs1);
            *reinterpret_cast<float2*>(&C[(size_t)r0 * NN + cc]) = v0;
            *reinterpret_cast<float2*>(&C[(size_t)(r0 + 8) * NN + cc]) = v1;
        }
    }
}

// ---------------- launch ----------------
extern "C" void kernel_launch(void* const* d_in, const int* in_sizes, int n_in,
                              void* d_out, int out_size) {
    const float* x  = (const float*)d_in[0];
    const float* w1 = (const float*)d_in[1];
    const float* cw = (const float*)d_in[2];
    const float* cb = (const float*)d_in[3];
    const float* w2 = (const float*)d_in[4];
    float* out = (float*)d_out;
    (void)in_sizes; (void)n_in; (void)out_size;

    static int inited = 0;
    if (!inited) {
        cudaFuncSetAttribute(gemm_bf16<0, DH, DM>, cudaFuncAttributeMaxDynamicSharedMemorySize, GSMEM_TOTAL);
        cudaFuncSetAttribute(gemm_bf16<1, DM, DH>, cudaFuncAttributeMaxDynamicSharedMemorySize, GSMEM_TOTAL);
        inited = 1;
    }

    wsum_all<<<8192, 256>>>(w1, w2);                                            // 1
    quant_all<<<16384, 256>>>(w1, w2, x);                                       // 2
    gemm_bf16<0, DH, DM><<<dim3(DH / BN, MM / BM), 128, GSMEM_TOTAL>>>(nullptr);// 3
    conv_silu_quant4<<<MM / 4, 512>>>(cw, cb);                                  // 4
    gemm_bf16<1, DM, DH><<<dim3(DM / BN, MM / BM), 128, GSMEM_TOTAL>>>(out);    // 5
}

// round 15
// speedup vs baseline: 1.0348x; 1.0196x over previous
#include <cuda_runtime.h>
#include <cuda_bf16.h>
#include <cstdint>
#include <math.h>

#define SS 2048
#define DM 1024
#define DH 4096
#define MM 8192

// ---------------- device scratch ----------------
__device__ double g_partial[8192];
__device__ float  g_wscale[4];
__device__ unsigned int g_wsum_count;
__device__ __align__(16) __nv_bfloat16 g_xq [(size_t)MM * DM];
__device__ __align__(16) __nv_bfloat16 g_wq1[(size_t)DH * DM];
__device__ __align__(16) __nv_bfloat16 g_wq2[(size_t)DM * DH];
__device__ __align__(16) __nv_bfloat16 g_q2 [(size_t)MM * DH];
__device__ __align__(16) float  g_h  [(size_t)MM * DH];
__device__ float g_rowscale1[MM];
__device__ float g_rowscale2[MM];

// ---------------- helpers ----------------
__device__ __forceinline__ uint32_t pack_bf16(float a, float b) {
    __nv_bfloat162 h = __floats2bfloat162_rn(a, b);
    return *reinterpret_cast<uint32_t*>(&h);
}
__device__ __forceinline__ float block_max(float v, float* sred, int tid, int nthr) {
    #pragma unroll
    for (int o = 16; o > 0; o >>= 1) v = fmaxf(v, __shfl_xor_sync(0xFFFFFFFFu, v, o));
    if ((tid & 31) == 0) sred[tid >> 5] = v;
    __syncthreads();
    int nw = nthr >> 5;
    if (tid < 32) {
        float x = (tid < nw) ? sred[tid] : 0.0f;
        #pragma unroll
        for (int o = 16; o > 0; o >>= 1) x = fmaxf(x, __shfl_xor_sync(0xFFFFFFFFu, x, o));
        if (tid == 0) sred[0] = x;
    }
    __syncthreads();
    float r = sred[0];
    __syncthreads();
    return r;
}
__device__ __forceinline__ float qr(float v, float s, float lo, float hi) {
    return fminf(fmaxf(rintf(v * s), lo), hi);
}

// ---------------- weight mean|w| : partial + last-block final (deterministic) ----------------
__global__ void wsum_all(const float* __restrict__ w1, const float* __restrict__ w2) {
    __shared__ double sd[256];
    __shared__ int slast;
    int blk = blockIdx.x;
    const float* src = (blk < 4096) ? (w1 + (size_t)blk * 1024)
                                    : (w2 + (size_t)(blk - 4096) * 1024);
    int tid = threadIdx.x;
    float4 v = reinterpret_cast<const float4*>(src)[tid];
    double s = ((double)fabsf(v.x) + (double)fabsf(v.y)) +
               ((double)fabsf(v.z) + (double)fabsf(v.w));
    sd[tid] = s; __syncthreads();
    for (int o = 128; o > 0; o >>= 1) { if (tid < o) sd[tid] += sd[tid + o]; __syncthreads(); }
    if (tid == 0) {
        g_partial[blk] = sd[0];
        __threadfence();
        unsigned int old = atomicAdd(&g_wsum_count, 1u);
        slast = (old == 8191u);
    }
    __syncthreads();
    if (slast) {
        for (int a = 0; a < 2; a++) {
            double t = 0.0;
            for (int i = tid; i < 4096; i += 256) t += g_partial[a * 4096 + i];
            sd[tid] = t; __syncthreads();
            for (int o = 128; o > 0; o >>= 1) { if (tid < o) sd[tid] += sd[tid + o]; __syncthreads(); }
            if (tid == 0) {
                float mean = (float)(sd[0] / (4096.0 * 1024.0));
                float mc = fmaxf(mean, 1e-5f);
                g_wscale[a]     = mc;
                g_wscale[2 + a] = 1.0f / mc;
            }
            __syncthreads();
        }
        if (tid == 0) g_wsum_count = 0;   // reset: every launch does identical work
    }
}

// ---------------- fused quantization: w1 | w2 | x -> bf16 ----------------
__global__ void __launch_bounds__(256) quant_all(const float* __restrict__ w1,
                                                 const float* __restrict__ w2,
                                                 const float* __restrict__ x) {
    __shared__ float sred[32];
    int blk = blockIdx.x, tid = threadIdx.x;
    if (blk < 8192) {
        int which = (blk >= 4096);
        const float* src = which ? w2 : w1;
        __nv_bfloat16* dst = which ? g_wq2 : g_wq1;
        size_t idx = (size_t)(blk & 4095) * 1024 + (size_t)tid * 4;
        float sw = g_wscale[2 + which];
        float4 v = *reinterpret_cast<const float4*>(src + idx);
        uint2 p = make_uint2(pack_bf16(qr(v.x, sw, -1.f, 1.f), qr(v.y, sw, -1.f, 1.f)),
                             pack_bf16(qr(v.z, sw, -1.f, 1.f), qr(v.w, sw, -1.f, 1.f)));
        *reinterpret_cast<uint2*>(dst + idx) = p;
    } else {
        int m = blk - 8192;
        float4 v = reinterpret_cast<const float4*>(x + (size_t)m * DM)[tid];
        float amax = fmaxf(fmaxf(fabsf(v.x), fabsf(v.y)), fmaxf(fabsf(v.z), fabsf(v.w)));
        amax = block_max(amax, sred, tid, 256);
        float s = 127.0f / fmaxf(amax, 1e-5f);
        uint2 p = make_uint2(pack_bf16(qr(v.x, s, -128.f, 127.f), qr(v.y, s, -128.f, 127.f)),
                             pack_bf16(qr(v.z, s, -128.f, 127.f), qr(v.w, s, -128.f, 127.f)));
        *reinterpret_cast<uint2*>(g_xq + (size_t)m * DM + (size_t)tid * 4) = p;
        if (tid == 0) g_rowscale1[m] = 1.0f / s;
    }
}

// ---------------- conv3 + SiLU + per-token quant, 4 tokens/block, 1024 threads ----------------
// Thread owns 4 channels (one float4 per row) -> ~half the register state of the
// 8-channel version; one 1024-thread block = 32 warps/SM (2x latency hiding).
__global__ void __launch_bounds__(1024, 1) conv_silu_quant4(const float* __restrict__ cw,
                                                            const float* __restrict__ cb) {
    __shared__ float sred4[32][4];
    __shared__ float s2s[4];
    int g0 = blockIdx.x * 4;              // first token of group (never crosses batch)
    int tid = threadIdx.x;
    int c0 = tid * 4;
    int spos0 = g0 & (SS - 1);

    // conv weights / bias for these 4 channels
    float warr[12];
    #pragma unroll
    for (int i = 0; i < 3; i++) {
        float4 v = *reinterpret_cast<const float4*>(cw + (size_t)c0 * 3 + i * 4);
        warr[i*4+0]=v.x; warr[i*4+1]=v.y; warr[i*4+2]=v.z; warr[i*4+3]=v.w;
    }
    float bv[4];
    {
        float4 v = *reinterpret_cast<const float4*>(cb + c0);
        bv[0]=v.x; bv[1]=v.y; bv[2]=v.z; bv[3]=v.w;
    }

    const float* hbase = g_h + (size_t)g0 * DH + c0;

    // 3-row sliding window (4 floats each)
    float w0r[4], w1r[4], w2r[4];
    {
        float4 vm = (spos0 > 0) ? *reinterpret_cast<const float4*>(hbase - DH)
                                : make_float4(0.f,0.f,0.f,0.f);
        w0r[0]=vm.x; w0r[1]=vm.y; w0r[2]=vm.z; w0r[3]=vm.w;
        float4 vc = *reinterpret_cast<const float4*>(hbase);
        w1r[0]=vc.x; w1r[1]=vc.y; w1r[2]=vc.z; w1r[3]=vc.w;
    }

    float y[4][4];
    float amax[4];
    #pragma unroll
    for (int t = 0; t < 4; t++) {
        bool valid = !(t == 3 && spos0 == SS - 4);
        {
            float4 vp = valid ? *reinterpret_cast<const float4*>(hbase + (size_t)(t + 1) * DH)
                              : make_float4(0.f,0.f,0.f,0.f);
            w2r[0]=vp.x; w2r[1]=vp.y; w2r[2]=vp.z; w2r[3]=vp.w;
        }
        float am = 0.0f;
        #pragma unroll
        for (int j = 0; j < 4; j++) {
            float v = bv[j];
            v = fmaf(warr[3*j+0], w0r[j], v);
            v = fmaf(warr[3*j+1], w1r[j], v);
            v = fmaf(warr[3*j+2], w2r[j], v);
            v = v / (1.0f + __expf(-v));      // SiLU (MUFU-based exp)
            y[t][j] = v;
            am = fmaxf(am, fabsf(v));
        }
        amax[t] = am;
        #pragma unroll
        for (int j = 0; j < 4; j++) { w0r[j] = w1r[j]; w1r[j] = w2r[j]; }
    }

    // fused 4-way block max over 32 warps
    #pragma unroll
    for (int t = 0; t < 4; t++) {
        float v = amax[t];
        #pragma unroll
        for (int o = 16; o > 0; o >>= 1) v = fmaxf(v, __shfl_xor_sync(0xFFFFFFFFu, v, o));
        if ((tid & 31) == 0) sred4[tid >> 5][t] = v;
    }
    __syncthreads();
    if (tid < 128) {                     // warps 0..3 finalize t = warp id
        int w = tid >> 5, lane = tid & 31;
        float v = sred4[lane][w];
        #pragma unroll
        for (int o = 16; o > 0; o >>= 1) v = fmaxf(v, __shfl_xor_sync(0xFFFFFFFFu, v, o));
        if (lane == 0) {
            float s2 = 127.0f / fmaxf(v, 1e-5f);
            s2s[w] = s2;
            g_rowscale2[g0 + w] = 1.0f / s2;
        }
    }
    __syncthreads();

    #pragma unroll
    for (int t = 0; t < 4; t++) {
        float s2 = s2s[t];
        uint2 p;
        p.x = pack_bf16(qr(y[t][0], s2, -128.f, 127.f), qr(y[t][1], s2, -128.f, 127.f));
        p.y = pack_bf16(qr(y[t][2], s2, -128.f, 127.f), qr(y[t][3], s2, -128.f, 127.f));
        *reinterpret_cast<uint2*>(g_q2 + (size_t)(g0 + t) * DH + c0) = p;
    }
}

// ====== bf16 HMMA GEMM: 128x128 block, 128 threads, 64x64 warp tiles ======
// 2 CTAs/SM, 3-stage cp.async, ks-level fragment double-buffering.
// (R12 configuration — known good at 485.4us; do not touch.)
#define BM 128
#define BN 128
#define BK 64                      // 64 bf16 = 128 bytes per smem row
#define STAGES 3
#define TILE_BYTES (128 * 128)     // 16 KB per operand tile
#define STAGE_BYTES (2 * TILE_BYTES)
#define GSMEM_TOTAL (STAGES * STAGE_BYTES)   // 96 KB

__device__ __forceinline__ void cp_async16(uint32_t saddr, const void* g) {
    asm volatile("cp.async.cg.shared.global [%0], [%1], 16;\n" :: "r"(saddr), "l"(g));
}
__device__ __forceinline__ void cp_commit() { asm volatile("cp.async.commit_group;\n"); }
__device__ __forceinline__ void cp_wait1()  { asm volatile("cp.async.wait_group 1;\n"); }

__device__ __forceinline__ void ldm_x4(uint32_t* r, uint32_t saddr) {
    asm volatile("ldmatrix.sync.aligned.m8n8.x4.shared.b16 {%0,%1,%2,%3}, [%4];\n"
        : "=r"(r[0]), "=r"(r[1]), "=r"(r[2]), "=r"(r[3]) : "r"(saddr));
}
__device__ __forceinline__ void mma16816(float* d, const uint32_t* a, const uint32_t* b) {
    asm volatile(
        "mma.sync.aligned.m16n8k16.row.col.f32.bf16.bf16.f32 "
        "{%0,%1,%2,%3},{%4,%5,%6,%7},{%8,%9},{%0,%1,%2,%3};\n"
        : "+f"(d[0]), "+f"(d[1]), "+f"(d[2]), "+f"(d[3])
        : "r"(a[0]), "r"(a[1]), "r"(a[2]), "r"(a[3]), "r"(b[0]), "r"(b[1]));
}

// load one 128x64 A tile + 128x64 B tile with 128 threads (16 cp each)
// 16B-chunk swizzle: phys = ch ^ (row&7)  -> conflict-free ldmatrix + stores
template <int KK>
__device__ __forceinline__ void load_stage(uint32_t sA, uint32_t sB,
                                           const __nv_bfloat16* Ag, const __nv_bfloat16* Bg,
                                           int kElem, int tid) {
    #pragma unroll
    for (int i = 0; i < 8; i++) {          // A: 1024 chunks
        int c = tid + i * 128;
        int row = c >> 3, ch = c & 7;
        int phys = ch ^ (row & 7);
        cp_async16(sA + row * 128 + phys * 16,
                   (const char*)(Ag + (size_t)row * KK + kElem) + ch * 16);
    }
    #pragma unroll
    for (int i = 0; i < 8; i++) {          // B: 1024 chunks
        int c = tid + i * 128;
        int row = c >> 3, ch = c & 7;
        int phys = ch ^ (row & 7);
        cp_async16(sB + row * 128 + phys * 16,
                   (const char*)(Bg + (size_t)row * KK + kElem) + ch * 16);
    }
    cp_commit();
}

// WHICH=0: A=g_xq B=g_wq1 C=g_h   WHICH=1: A=g_q2 B=g_wq2 C=out
template <int WHICH, int NN, int KK>
__global__ void __launch_bounds__(128, 2) gemm_bf16(float* __restrict__ Cout) {
    extern __shared__ __align__(16) char smem[];
    uint32_t s0 = (uint32_t)__cvta_generic_to_shared(smem);

    const __nv_bfloat16* A  = WHICH ? g_q2 : g_xq;
    const __nv_bfloat16* B  = WHICH ? g_wq2 : g_wq1;
    float*               C  = WHICH ? Cout : g_h;
    const float*         rs = WHICH ? g_rowscale2 : g_rowscale1;

    const int tid = threadIdx.x, lane = tid & 31, wid = tid >> 5;
    const int wm = (wid >> 1) * 64, wn = (wid & 1) * 64;   // 2x2 warp grid, 64x64 tiles
    const int m0 = blockIdx.y * BM, n0 = blockIdx.x * BN;

    const __nv_bfloat16* Ag = A + (size_t)m0 * KK;
    const __nv_bfloat16* Bg = B + (size_t)n0 * KK;

    // ldmatrix per-lane base addressing (proven R7 pattern)
    const int rA = wm + (lane & 15);           // + im*16
    const int hiA = lane >> 4;                 // k-half select
    const int xA = rA & 7;
    const int gB = lane >> 3, lrB = lane & 7;
    const int rB = wn + ((gB & 2) << 2) + lrB; // + jp*16
    const int hiB = gB & 1;
    const int xB = rB & 7;

    float acc[4][8][4];
    #pragma unroll
    for (int im = 0; im < 4; im++)
        #pragma unroll
        for (int jn = 0; jn < 8; jn++)
            #pragma unroll
            for (int q = 0; q < 4; q++) acc[im][jn][q] = 0.0f;

    uint32_t af[2][4][4], bf[2][4][4];   // double-buffered fragments

    constexpr int KT = KK / BK;
    #pragma unroll
    for (int p = 0; p < STAGES - 1; p++)
        load_stage<KK>(s0 + p * STAGE_BYTES, s0 + p * STAGE_BYTES + TILE_BYTES,
                       Ag, Bg, p * BK, tid);

    for (int kt = 0; kt < KT; kt++) {
        cp_wait1();                 // stage kt resident
        __syncthreads();            // all warps done with buffer about to be refilled

        const uint32_t sA = s0 + (uint32_t)(kt % STAGES) * STAGE_BYTES;
        const uint32_t sB = sA + TILE_BYTES;
        const uint32_t aL = sA + (uint32_t)rA * 128;
        const uint32_t bL = sB + (uint32_t)rB * 128;

        // ks=0 fragments first (gets LDSM started before the cp.async burst)
        {
            const uint32_t ofA = (uint32_t)((hiA ^ xA) << 4);
            #pragma unroll
            for (int im = 0; im < 4; im++)
                ldm_x4(af[0][im], aL + (uint32_t)(im * 16 * 128) + ofA);
            const uint32_t ofB = (uint32_t)((hiB ^ xB) << 4);
            #pragma unroll
            for (int jp = 0; jp < 4; jp++)
                ldm_x4(bf[0][jp], bL + (uint32_t)(jp * 16 * 128) + ofB);
        }

        // prefetch stage kt+2
        {
            int nk = kt + STAGES - 1;
            if (nk < KT) {
                int pb = nk % STAGES;
                load_stage<KK>(s0 + pb * STAGE_BYTES, s0 + pb * STAGE_BYTES + TILE_BYTES,
                               Ag, Bg, nk * BK, tid);
            } else {
                cp_commit();        // keep group accounting uniform
            }
        }

        #pragma unroll
        for (int ks = 0; ks < 4; ks++) {
            const int cur = ks & 1;
            if (ks < 3) {           // prefetch next k-chunk fragments
                const int nxt = cur ^ 1;
                const uint32_t ofA = (uint32_t)((((ks + 1) * 2 + hiA) ^ xA) << 4);
                #pragma unroll
                for (int im = 0; im < 4; im++)
                    ldm_x4(af[nxt][im], aL + (uint32_t)(im * 16 * 128) + ofA);
                const uint32_t ofB = (uint32_t)((((ks + 1) * 2 + hiB) ^ xB) << 4);
                #pragma unroll
                for (int jp = 0; jp < 4; jp++)
                    ldm_x4(bf[nxt][jp], bL + (uint32_t)(jp * 16 * 128) + ofB);
            }
            #pragma unroll
            for (int im = 0; im < 4; im++)
                #pragma unroll
                for (int jn = 0; jn < 8; jn++)
                    mma16816(acc[im][jn], af[cur][im], &bf[cur][jn >> 1][(jn & 1) * 2]);
        }
    }

    const float ws = g_wscale[WHICH];
    const int g = lane >> 2, t = lane & 3;
    #pragma unroll
    for (int im = 0; im < 4; im++) {
        int r0 = m0 + wm + im * 16 + g;
        float rs0 = rs[r0] * ws;
        float rs1 = rs[r0 + 8] * ws;
        #pragma unroll
        for (int jn = 0; jn < 8; jn++) {
            int cc = n0 + wn + jn * 8 + t * 2;
            float2 v0 = make_float2(acc[im][jn][0] * rs0, acc[im][jn][1] * rs0);
            float2 v1 = make_float2(acc[im][jn][2] * rs1, acc[im][jn][3] * rs1);
            *reinterpret_cast<float2*>(&C[(size_t)r0 * NN + cc]) = v0;
            *reinterpret_cast<float2*>(&C[(size_t)(r0 + 8) * NN + cc]) = v1;
        }
    }
}

// ---------------- launch ----------------
extern "C" void kernel_launch(void* const* d_in, const int* in_sizes, int n_in,
                              void* d_out, int out_size) {
    const float* x  = (const float*)d_in[0];
    const float* w1 = (const float*)d_in[1];
    const float* cw = (const float*)d_in[2];
    const float* cb = (const float*)d_in[3];
    const float* w2 = (const float*)d_in[4];
    float* out = (float*)d_out;
    (void)in_sizes; (void)n_in; (void)out_size;

    static int inited = 0;
    if (!inited) {
        cudaFuncSetAttribute(gemm_bf16<0, DH, DM>, cudaFuncAttributeMaxDynamicSharedMemorySize, GSMEM_TOTAL);
        cudaFuncSetAttribute(gemm_bf16<1, DM, DH>, cudaFuncAttributeMaxDynamicSharedMemorySize, GSMEM_TOTAL);
        inited = 1;
    }

    wsum_all<<<8192, 256>>>(w1, w2);                                            // 1
    quant_all<<<16384, 256>>>(w1, w2, x);                                       // 2
    gemm_bf16<0, DH, DM><<<dim3(DH / BN, MM / BM), 128, GSMEM_TOTAL>>>(nullptr);// 3
    conv_silu_quant4<<<MM / 4, 1024>>>(cw, cb);                                 // 4
    gemm_bf16<1, DM, DH><<<dim3(DM / BN, MM / BM), 128, GSMEM_TOTAL>>>(out);    // 5
}

// round 16
// speedup vs baseline: 1.0595x; 1.0239x over previous
#include <cuda_runtime.h>
#include <cuda_bf16.h>
#include <cstdint>
#include <math.h>

#define SS 2048
#define DM 1024
#define DH 4096
#define MM 8192

// ---------------- device scratch ----------------
__device__ double g_partial[8192];
__device__ float  g_wscale[4];
__device__ unsigned int g_wsum_count;
__device__ __align__(16) __nv_bfloat16 g_xq [(size_t)MM * DM];
__device__ __align__(16) __nv_bfloat16 g_wq1[(size_t)DH * DM];
__device__ __align__(16) __nv_bfloat16 g_wq2[(size_t)DM * DH];
__device__ __align__(16) __nv_bfloat16 g_q2 [(size_t)MM * DH];
__device__ __align__(16) float  g_h  [(size_t)MM * DH];
__device__ float g_rowscale1[MM];
__device__ float g_rowscale2[MM];

// ---------------- helpers ----------------
__device__ __forceinline__ uint32_t pack_bf16(float a, float b) {
    __nv_bfloat162 h = __floats2bfloat162_rn(a, b);
    return *reinterpret_cast<uint32_t*>(&h);
}
__device__ __forceinline__ float block_max(float v, float* sred, int tid, int nthr) {
    #pragma unroll
    for (int o = 16; o > 0; o >>= 1) v = fmaxf(v, __shfl_xor_sync(0xFFFFFFFFu, v, o));
    if ((tid & 31) == 0) sred[tid >> 5] = v;
    __syncthreads();
    int nw = nthr >> 5;
    if (tid < 32) {
        float x = (tid < nw) ? sred[tid] : 0.0f;
        #pragma unroll
        for (int o = 16; o > 0; o >>= 1) x = fmaxf(x, __shfl_xor_sync(0xFFFFFFFFu, x, o));
        if (tid == 0) sred[0] = x;
    }
    __syncthreads();
    float r = sred[0];
    __syncthreads();
    return r;
}
__device__ __forceinline__ float qr(float v, float s, float lo, float hi) {
    return fminf(fmaxf(rintf(v * s), lo), hi);
}

// ---------------- weight mean|w| : partial + last-block final (deterministic) ----------------
__global__ void wsum_all(const float* __restrict__ w1, const float* __restrict__ w2) {
    __shared__ double sd[256];
    __shared__ int slast;
    int blk = blockIdx.x;
    const float* src = (blk < 4096) ? (w1 + (size_t)blk * 1024)
                                    : (w2 + (size_t)(blk - 4096) * 1024);
    int tid = threadIdx.x;
    float4 v = reinterpret_cast<const float4*>(src)[tid];
    double s = ((double)fabsf(v.x) + (double)fabsf(v.y)) +
               ((double)fabsf(v.z) + (double)fabsf(v.w));
    sd[tid] = s; __syncthreads();
    for (int o = 128; o > 0; o >>= 1) { if (tid < o) sd[tid] += sd[tid + o]; __syncthreads(); }
    if (tid == 0) {
        g_partial[blk] = sd[0];
        __threadfence();
        unsigned int old = atomicAdd(&g_wsum_count, 1u);
        slast = (old == 8191u);
    }
    __syncthreads();
    if (slast) {
        for (int a = 0; a < 2; a++) {
            double t = 0.0;
            for (int i = tid; i < 4096; i += 256) t += g_partial[a * 4096 + i];
            sd[tid] = t; __syncthreads();
            for (int o = 128; o > 0; o >>= 1) { if (tid < o) sd[tid] += sd[tid + o]; __syncthreads(); }
            if (tid == 0) {
                float mean = (float)(sd[0] / (4096.0 * 1024.0));
                float mc = fmaxf(mean, 1e-5f);
                g_wscale[a]     = mc;
                g_wscale[2 + a] = 1.0f / mc;
            }
            __syncthreads();
        }
        if (tid == 0) g_wsum_count = 0;   // reset: every launch does identical work
    }
}

// ---------------- fused quantization: w1 | w2 | x -> bf16 ----------------
__global__ void __launch_bounds__(256) quant_all(const float* __restrict__ w1,
                                                 const float* __restrict__ w2,
                                                 const float* __restrict__ x) {
    __shared__ float sred[32];
    int blk = blockIdx.x, tid = threadIdx.x;
    if (blk < 8192) {
        int which = (blk >= 4096);
        const float* src = which ? w2 : w1;
        __nv_bfloat16* dst = which ? g_wq2 : g_wq1;
        size_t idx = (size_t)(blk & 4095) * 1024 + (size_t)tid * 4;
        float sw = g_wscale[2 + which];
        float4 v = *reinterpret_cast<const float4*>(src + idx);
        uint2 p = make_uint2(pack_bf16(qr(v.x, sw, -1.f, 1.f), qr(v.y, sw, -1.f, 1.f)),
                             pack_bf16(qr(v.z, sw, -1.f, 1.f), qr(v.w, sw, -1.f, 1.f)));
        *reinterpret_cast<uint2*>(dst + idx) = p;
    } else {
        int m = blk - 8192;
        float4 v = reinterpret_cast<const float4*>(x + (size_t)m * DM)[tid];
        float amax = fmaxf(fmaxf(fabsf(v.x), fabsf(v.y)), fmaxf(fabsf(v.z), fabsf(v.w)));
        amax = block_max(amax, sred, tid, 256);
        float s = 127.0f / fmaxf(amax, 1e-5f);
        uint2 p = make_uint2(pack_bf16(qr(v.x, s, -128.f, 127.f), qr(v.y, s, -128.f, 127.f)),
                             pack_bf16(qr(v.z, s, -128.f, 127.f), qr(v.w, s, -128.f, 127.f)));
        *reinterpret_cast<uint2*>(g_xq + (size_t)m * DM + (size_t)tid * 4) = p;
        if (tid == 0) g_rowscale1[m] = 1.0f / s;
    }
}

// ---------------- conv3 + SiLU + per-token quant, 4 tokens/block, 1024 threads ----------------
// Thread owns 4 channels; double-buffered next-row load so the row t+3 fetch
// issues before token t's compute (hides DRAM latency behind the FMA/exp chain).
__global__ void __launch_bounds__(1024, 1) conv_silu_quant4(const float* __restrict__ cw,
                                                            const float* __restrict__ cb) {
    __shared__ float sred4[32][4];
    __shared__ float s2s[4];
    int g0 = blockIdx.x * 4;              // first token of group (never crosses batch)
    int tid = threadIdx.x;
    int c0 = tid * 4;
    int spos0 = g0 & (SS - 1);

    // conv weights / bias for these 4 channels
    float warr[12];
    #pragma unroll
    for (int i = 0; i < 3; i++) {
        float4 v = *reinterpret_cast<const float4*>(cw + (size_t)c0 * 3 + i * 4);
        warr[i*4+0]=v.x; warr[i*4+1]=v.y; warr[i*4+2]=v.z; warr[i*4+3]=v.w;
    }
    float bv[4];
    {
        float4 v = *reinterpret_cast<const float4*>(cb + c0);
        bv[0]=v.x; bv[1]=v.y; bv[2]=v.z; bv[3]=v.w;
    }

    const float* hbase = g_h + (size_t)g0 * DH + c0;

    // rows: row r = token g0-1+r. Upfront: row0 (t-1), row1 (t0), row2 (t0+1).
    float w0r[4], w1r[4], nxt[4];
    {
        float4 vm = (spos0 > 0) ? *reinterpret_cast<const float4*>(hbase - DH)
                                : make_float4(0.f,0.f,0.f,0.f);
        float4 vc = *reinterpret_cast<const float4*>(hbase);
        float4 vn = *reinterpret_cast<const float4*>(hbase + DH);   // always valid (spos0 <= SS-4)
        w0r[0]=vm.x; w0r[1]=vm.y; w0r[2]=vm.z; w0r[3]=vm.w;
        w1r[0]=vc.x; w1r[1]=vc.y; w1r[2]=vc.z; w1r[3]=vc.w;
        nxt[0]=vn.x; nxt[1]=vn.y; nxt[2]=vn.z; nxt[3]=vn.w;
    }

    float y[4][4];
    float amax[4];
    #pragma unroll
    for (int t = 0; t < 4; t++) {
        float w2r[4];
        #pragma unroll
        for (int j = 0; j < 4; j++) w2r[j] = nxt[j];
        // issue next row load (row t+3 = token g0+t+2) BEFORE compute
        if (t < 3) {
            bool valid = !(t == 2 && spos0 == SS - 4);
            float4 vn = valid ? *reinterpret_cast<const float4*>(hbase + (size_t)(t + 2) * DH)
                              : make_float4(0.f,0.f,0.f,0.f);
            nxt[0]=vn.x; nxt[1]=vn.y; nxt[2]=vn.z; nxt[3]=vn.w;
        }
        float am = 0.0f;
        #pragma unroll
        for (int j = 0; j < 4; j++) {
            float v = bv[j];
            v = fmaf(warr[3*j+0], w0r[j], v);
            v = fmaf(warr[3*j+1], w1r[j], v);
            v = fmaf(warr[3*j+2], w2r[j], v);
            v = v / (1.0f + __expf(-v));      // SiLU (MUFU-based exp)
            y[t][j] = v;
            am = fmaxf(am, fabsf(v));
        }
        amax[t] = am;
        #pragma unroll
        for (int j = 0; j < 4; j++) { w0r[j] = w1r[j]; w1r[j] = w2r[j]; }
    }

    // fused 4-way block max over 32 warps
    #pragma unroll
    for (int t = 0; t < 4; t++) {
        float v = amax[t];
        #pragma unroll
        for (int o = 16; o > 0; o >>= 1) v = fmaxf(v, __shfl_xor_sync(0xFFFFFFFFu, v, o));
        if ((tid & 31) == 0) sred4[tid >> 5][t] = v;
    }
    __syncthreads();
    if (tid < 128) {                     // warps 0..3 finalize t = warp id
        int w = tid >> 5, lane = tid & 31;
        float v = sred4[lane][w];
        #pragma unroll
        for (int o = 16; o > 0; o >>= 1) v = fmaxf(v, __shfl_xor_sync(0xFFFFFFFFu, v, o));
        if (lane == 0) {
            float s2 = 127.0f / fmaxf(v, 1e-5f);
            s2s[w] = s2;
            g_rowscale2[g0 + w] = 1.0f / s2;
        }
    }
    __syncthreads();

    #pragma unroll
    for (int t = 0; t < 4; t++) {
        float s2 = s2s[t];
        uint2 p;
        p.x = pack_bf16(qr(y[t][0], s2, -128.f, 127.f), qr(y[t][1], s2, -128.f, 127.f));
        p.y = pack_bf16(qr(y[t][2], s2, -128.f, 127.f), qr(y[t][3], s2, -128.f, 127.f));
        *reinterpret_cast<uint2*>(g_q2 + (size_t)(g0 + t) * DH + c0) = p;
    }
}

// ====== bf16 HMMA GEMM: 128x128 block, 128 threads, 64x64 warp tiles ======
// 2 CTAs/SM, 3-stage cp.async, ks-level fragment double-buffering.
// (R12 configuration — known good; do not touch.)
#define BM 128
#define BN 128
#define BK 64                      // 64 bf16 = 128 bytes per smem row
#define STAGES 3
#define TILE_BYTES (128 * 128)     // 16 KB per operand tile
#define STAGE_BYTES (2 * TILE_BYTES)
#define GSMEM_TOTAL (STAGES * STAGE_BYTES)   // 96 KB

__device__ __forceinline__ void cp_async16(uint32_t saddr, const void* g) {
    asm volatile("cp.async.cg.shared.global [%0], [%1], 16;\n" :: "r"(saddr), "l"(g));
}
__device__ __forceinline__ void cp_commit() { asm volatile("cp.async.commit_group;\n"); }
__device__ __forceinline__ void cp_wait1()  { asm volatile("cp.async.wait_group 1;\n"); }

__device__ __forceinline__ void ldm_x4(uint32_t* r, uint32_t saddr) {
    asm volatile("ldmatrix.sync.aligned.m8n8.x4.shared.b16 {%0,%1,%2,%3}, [%4];\n"
        : "=r"(r[0]), "=r"(r[1]), "=r"(r[2]), "=r"(r[3]) : "r"(saddr));
}
__device__ __forceinline__ void mma16816(float* d, const uint32_t* a, const uint32_t* b) {
    asm volatile(
        "mma.sync.aligned.m16n8k16.row.col.f32.bf16.bf16.f32 "
        "{%0,%1,%2,%3},{%4,%5,%6,%7},{%8,%9},{%0,%1,%2,%3};\n"
        : "+f"(d[0]), "+f"(d[1]), "+f"(d[2]), "+f"(d[3])
        : "r"(a[0]), "r"(a[1]), "r"(a[2]), "r"(a[3]), "r"(b[0]), "r"(b[1]));
}

// load one 128x64 A tile + 128x64 B tile with 128 threads (16 cp each)
// 16B-chunk swizzle: phys = ch ^ (row&7)  -> conflict-free ldmatrix + stores
template <int KK>
__device__ __forceinline__ void load_stage(uint32_t sA, uint32_t sB,
                                           const __nv_bfloat16* Ag, const __nv_bfloat16* Bg,
                                           int kElem, int tid) {
    #pragma unroll
    for (int i = 0; i < 8; i++) {          // A: 1024 chunks
        int c = tid + i * 128;
        int row = c >> 3, ch = c & 7;
        int phys = ch ^ (row & 7);
        cp_async16(sA + row * 128 + phys * 16,
                   (const char*)(Ag + (size_t)row * KK + kElem) + ch * 16);
    }
    #pragma unroll
    for (int i = 0; i < 8; i++) {          // B: 1024 chunks
        int c = tid + i * 128;
        int row = c >> 3, ch = c & 7;
        int phys = ch ^ (row & 7);
        cp_async16(sB + row * 128 + phys * 16,
                   (const char*)(Bg + (size_t)row * KK + kElem) + ch * 16);
    }
    cp_commit();
}

// WHICH=0: A=g_xq B=g_wq1 C=g_h   WHICH=1: A=g_q2 B=g_wq2 C=out
template <int WHICH, int NN, int KK>
__global__ void __launch_bounds__(128, 2) gemm_bf16(float* __restrict__ Cout) {
    extern __shared__ __align__(16) char smem[];
    uint32_t s0 = (uint32_t)__cvta_generic_to_shared(smem);

    const __nv_bfloat16* A  = WHICH ? g_q2 : g_xq;
    const __nv_bfloat16* B  = WHICH ? g_wq2 : g_wq1;
    float*               C  = WHICH ? Cout : g_h;
    const float*         rs = WHICH ? g_rowscale2 : g_rowscale1;

    const int tid = threadIdx.x, lane = tid & 31, wid = tid >> 5;
    const int wm = (wid >> 1) * 64, wn = (wid & 1) * 64;   // 2x2 warp grid, 64x64 tiles
    const int m0 = blockIdx.y * BM, n0 = blockIdx.x * BN;

    const __nv_bfloat16* Ag = A + (size_t)m0 * KK;
    const __nv_bfloat16* Bg = B + (size_t)n0 * KK;

    // ldmatrix per-lane base addressing (proven R7 pattern)
    const int rA = wm + (lane & 15);           // + im*16
    const int hiA = lane >> 4;                 // k-half select
    const int xA = rA & 7;
    const int gB = lane >> 3, lrB = lane & 7;
    const int rB = wn + ((gB & 2) << 2) + lrB; // + jp*16
    const int hiB = gB & 1;
    const int xB = rB & 7;

    float acc[4][8][4];
    #pragma unroll
    for (int im = 0; im < 4; im++)
        #pragma unroll
        for (int jn = 0; jn < 8; jn++)
            #pragma unroll
            for (int q = 0; q < 4; q++) acc[im][jn][q] = 0.0f;

    uint32_t af[2][4][4], bf[2][4][4];   // double-buffered fragments

    constexpr int KT = KK / BK;
    #pragma unroll
    for (int p = 0; p < STAGES - 1; p++)
        load_stage<KK>(s0 + p * STAGE_BYTES, s0 + p * STAGE_BYTES + TILE_BYTES,
                       Ag, Bg, p * BK, tid);

    for (int kt = 0; kt < KT; kt++) {
        cp_wait1();                 // stage kt resident
        __syncthreads();            // all warps done with buffer about to be refilled

        const uint32_t sA = s0 + (uint32_t)(kt % STAGES) * STAGE_BYTES;
        const uint32_t sB = sA + TILE_BYTES;
        const uint32_t aL = sA + (uint32_t)rA * 128;
        const uint32_t bL = sB + (uint32_t)rB * 128;

        // ks=0 fragments first (gets LDSM started before the cp.async burst)
        {
            const uint32_t ofA = (uint32_t)((hiA ^ xA) << 4);
            #pragma unroll
            for (int im = 0; im < 4; im++)
                ldm_x4(af[0][im], aL + (uint32_t)(im * 16 * 128) + ofA);
            const uint32_t ofB = (uint32_t)((hiB ^ xB) << 4);
            #pragma unroll
            for (int jp = 0; jp < 4; jp++)
                ldm_x4(bf[0][jp], bL + (uint32_t)(jp * 16 * 128) + ofB);
        }

        // prefetch stage kt+2
        {
            int nk = kt + STAGES - 1;
            if (nk < KT) {
                int pb = nk % STAGES;
                load_stage<KK>(s0 + pb * STAGE_BYTES, s0 + pb * STAGE_BYTES + TILE_BYTES,
                               Ag, Bg, nk * BK, tid);
            } else {
                cp_commit();        // keep group accounting uniform
            }
        }

        #pragma unroll
        for (int ks = 0; ks < 4; ks++) {
            const int cur = ks & 1;
            if (ks < 3) {           // prefetch next k-chunk fragments
                const int nxt = cur ^ 1;
                const uint32_t ofA = (uint32_t)((((ks + 1) * 2 + hiA) ^ xA) << 4);
                #pragma unroll
                for (int im = 0; im < 4; im++)
                    ldm_x4(af[nxt][im], aL + (uint32_t)(im * 16 * 128) + ofA);
                const uint32_t ofB = (uint32_t)((((ks + 1) * 2 + hiB) ^ xB) << 4);
                #pragma unroll
                for (int jp = 0; jp < 4; jp++)
                    ldm_x4(bf[nxt][jp], bL + (uint32_t)(jp * 16 * 128) + ofB);
            }
            #pragma unroll
            for (int im = 0; im < 4; im++)
                #pragma unroll
                for (int jn = 0; jn < 8; jn++)
                    mma16816(acc[im][jn], af[cur][im], &bf[cur][jn >> 1][(jn & 1) * 2]);
        }
    }

    const float ws = g_wscale[WHICH];
    const int g = lane >> 2, t = lane & 3;
    #pragma unroll
    for (int im = 0; im < 4; im++) {
        int r0 = m0 + wm + im * 16 + g;
        float rs0 = rs[r0] * ws;
        float rs1 = rs[r0 + 8] * ws;
        #pragma unroll
        for (int jn = 0; jn < 8; jn++) {
            int cc = n0 + wn + jn * 8 + t * 2;
            float2 v0 = make_float2(acc[im][jn][0] * rs0, acc[im][jn][1] * rs0);
            float2 v1 = make_float2(acc[im][jn][2] * rs1, acc[im][jn][3] * rs1);
            *reinterpret_cast<float2*>(&C[(size_t)r0 * NN + cc]) = v0;
            *reinterpret_cast<float2*>(&C[(size_t)(r0 + 8) * NN + cc]) = v1;
        }
    }
}

// ---------------- launch ----------------
extern "C" void kernel_launch(void* const* d_in, const int* in_sizes, int n_in,
                              void* d_out, int out_size) {
    const float* x  = (const float*)d_in[0];
    const float* w1 = (const float*)d_in[1];
    const float* cw = (const float*)d_in[2];
    const float* cb = (const float*)d_in[3];
    const float* w2 = (const float*)d_in[4];
    float* out = (float*)d_out;
    (void)in_sizes; (void)n_in; (void)out_size;

    static int inited = 0;
    if (!inited) {
        cudaFuncSetAttribute(gemm_bf16<0, DH, DM>, cudaFuncAttributeMaxDynamicSharedMemorySize, GSMEM_TOTAL);
        cudaFuncSetAttribute(gemm_bf16<1, DM, DH>, cudaFuncAttributeMaxDynamicSharedMemorySize, GSMEM_TOTAL);
        inited = 1;
    }

    wsum_all<<<8192, 256>>>(w1, w2);                                            // 1
    quant_all<<<16384, 256>>>(w1, w2, x);                                       // 2
    gemm_bf16<0, DH, DM><<<dim3(DH / BN, MM / BM), 128, GSMEM_TOTAL>>>(nullptr);// 3
    conv_silu_quant4<<<MM / 4, 1024>>>(cw, cb);                                 // 4
    gemm_bf16<1, DM, DH><<<dim3(DM / BN, MM / BM), 128, GSMEM_TOTAL>>>(out);    // 5
}

// round 17
// speedup vs baseline: 1.1024x; 1.0405x over previous
#include <cuda_runtime.h>
#include <cuda_bf16.h>
#include <cstdint>
#include <math.h>

#define SS 2048
#define DM 1024
#define DH 4096
#define MM 8192

// ---------------- device scratch ----------------
__device__ double g_partial[8192];
__device__ float  g_wscale[4];
__device__ unsigned int g_wsum_count;
__device__ __align__(16) __nv_bfloat16 g_xq [(size_t)MM * DM];
__device__ __align__(16) __nv_bfloat16 g_wq1[(size_t)DH * DM];
__device__ __align__(16) __nv_bfloat16 g_wq2[(size_t)DM * DH];
__device__ __align__(16) __nv_bfloat16 g_q2 [(size_t)MM * DH];
__device__ __align__(16) float  g_h  [(size_t)MM * DH];
__device__ float g_rowscale1[MM];
__device__ float g_rowscale2[MM];

// ---------------- helpers ----------------
__device__ __forceinline__ uint32_t pack_bf16(float a, float b) {
    __nv_bfloat162 h = __floats2bfloat162_rn(a, b);
    return *reinterpret_cast<uint32_t*>(&h);
}
__device__ __forceinline__ float qr(float v, float s, float lo, float hi) {
    return fminf(fmaxf(rintf(v * s), lo), hi);
}

// ---------------- weight mean|w| : MLP-2 partials + last-block final ----------------
// grid 4096: blocks 0-2047 cover w1 (2048 floats each), 2048-4095 cover w2.
__global__ void wsum_all(const float* __restrict__ w1, const float* __restrict__ w2) {
    __shared__ double sd[256];
    __shared__ int slast;
    int blk = blockIdx.x;
    const float* src = (blk < 2048) ? (w1 + (size_t)blk * 2048)
                                    : (w2 + (size_t)(blk - 2048) * 2048);
    int tid = threadIdx.x;
    float4 a = *reinterpret_cast<const float4*>(src + tid * 4);          // independent
    float4 b = *reinterpret_cast<const float4*>(src + 1024 + tid * 4);   // loads (MLP 2)
    double s = (((double)fabsf(a.x) + (double)fabsf(a.y)) +
                ((double)fabsf(a.z) + (double)fabsf(a.w))) +
               (((double)fabsf(b.x) + (double)fabsf(b.y)) +
                ((double)fabsf(b.z) + (double)fabsf(b.w)));
    sd[tid] = s; __syncthreads();
    for (int o = 128; o > 0; o >>= 1) { if (tid < o) sd[tid] += sd[tid + o]; __syncthreads(); }
    if (tid == 0) {
        g_partial[blk] = sd[0];
        __threadfence();
        unsigned int old = atomicAdd(&g_wsum_count, 1u);
        slast = (old == 4095u);
    }
    __syncthreads();
    if (slast) {
        for (int a2 = 0; a2 < 2; a2++) {
            double t = 0.0;
            for (int i = tid; i < 2048; i += 256) t += g_partial[a2 * 2048 + i];
            sd[tid] = t; __syncthreads();
            for (int o = 128; o > 0; o >>= 1) { if (tid < o) sd[tid] += sd[tid + o]; __syncthreads(); }
            if (tid == 0) {
                float mean = (float)(sd[0] / (4096.0 * 1024.0));
                float mc = fmaxf(mean, 1e-5f);
                g_wscale[a2]     = mc;
                g_wscale[2 + a2] = 1.0f / mc;
            }
            __syncthreads();
        }
        if (tid == 0) g_wsum_count = 0;   // reset: every launch does identical work
    }
}

// ---------------- fused quantization, MLP-boosted ----------------
// grid 6144: blocks 0-1023 w1 (4096 floats each, 4x float4/thread),
//            1024-2047 w2, 2048-6143 x (2 rows per block, 2x float4/thread).
__global__ void __launch_bounds__(256) quant_all(const float* __restrict__ w1,
                                                 const float* __restrict__ w2,
                                                 const float* __restrict__ x) {
    __shared__ float sred[8][2];
    __shared__ float ssc[2];
    int blk = blockIdx.x, tid = threadIdx.x;
    if (blk < 2048) {
        int which = (blk >= 1024);
        const float* src = which ? (w2 + (size_t)(blk - 1024) * 4096)
                                 : (w1 + (size_t)blk * 4096);
        __nv_bfloat16* dst = which ? (g_wq2 + (size_t)(blk - 1024) * 4096)
                                   : (g_wq1 + (size_t)blk * 4096);
        float sw = g_wscale[2 + which];
        float4 v[4];
        #pragma unroll
        for (int i = 0; i < 4; i++)        // 4 independent loads (MLP 4)
            v[i] = *reinterpret_cast<const float4*>(src + i * 1024 + tid * 4);
        #pragma unroll
        for (int i = 0; i < 4; i++) {
            uint2 p = make_uint2(pack_bf16(qr(v[i].x, sw, -1.f, 1.f), qr(v[i].y, sw, -1.f, 1.f)),
                                 pack_bf16(qr(v[i].z, sw, -1.f, 1.f), qr(v[i].w, sw, -1.f, 1.f)));
            *reinterpret_cast<uint2*>(dst + i * 1024 + tid * 4) = p;
        }
    } else {
        int m0 = (blk - 2048) * 2;
        int lane = tid & 31, wid = tid >> 5;
        float4 v0 = reinterpret_cast<const float4*>(x + (size_t)m0 * DM)[tid];       // MLP 2
        float4 v1 = reinterpret_cast<const float4*>(x + (size_t)(m0 + 1) * DM)[tid];
        float a0 = fmaxf(fmaxf(fabsf(v0.x), fabsf(v0.y)), fmaxf(fabsf(v0.z), fabsf(v0.w)));
        float a1 = fmaxf(fmaxf(fabsf(v1.x), fabsf(v1.y)), fmaxf(fabsf(v1.z), fabsf(v1.w)));
        #pragma unroll
        for (int o = 16; o > 0; o >>= 1) {
            a0 = fmaxf(a0, __shfl_xor_sync(0xFFFFFFFFu, a0, o));
            a1 = fmaxf(a1, __shfl_xor_sync(0xFFFFFFFFu, a1, o));
        }
        if (lane == 0) { sred[wid][0] = a0; sred[wid][1] = a1; }
        __syncthreads();
        if (wid < 2) {                     // warp w finalizes row w
            float v = (lane < 8) ? sred[lane][wid] : 0.0f;
            #pragma unroll
            for (int o = 4; o > 0; o >>= 1) v = fmaxf(v, __shfl_xor_sync(0xFFFFFFFFu, v, o));
            if (lane == 0) {
                float s = 127.0f / fmaxf(v, 1e-5f);
                ssc[wid] = s;
                g_rowscale1[m0 + wid] = 1.0f / s;
            }
        }
        __syncthreads();
        float s0 = ssc[0], s1 = ssc[1];
        uint2 p0 = make_uint2(pack_bf16(qr(v0.x, s0, -128.f, 127.f), qr(v0.y, s0, -128.f, 127.f)),
                              pack_bf16(qr(v0.z, s0, -128.f, 127.f), qr(v0.w, s0, -128.f, 127.f)));
        uint2 p1 = make_uint2(pack_bf16(qr(v1.x, s1, -128.f, 127.f), qr(v1.y, s1, -128.f, 127.f)),
                              pack_bf16(qr(v1.z, s1, -128.f, 127.f), qr(v1.w, s1, -128.f, 127.f)));
        *reinterpret_cast<uint2*>(g_xq + (size_t)m0 * DM + (size_t)tid * 4) = p0;
        *reinterpret_cast<uint2*>(g_xq + (size_t)(m0 + 1) * DM + (size_t)tid * 4) = p1;
    }
}

// ---------------- conv3 + SiLU + per-token quant, 4 tokens/block, 1024 threads ----------------
// (R16 configuration — known good at 64.1us; unchanged.)
__global__ void __launch_bounds__(1024, 1) conv_silu_quant4(const float* __restrict__ cw,
                                                            const float* __restrict__ cb) {
    __shared__ float sred4[32][4];
    __shared__ float s2s[4];
    int g0 = blockIdx.x * 4;              // first token of group (never crosses batch)
    int tid = threadIdx.x;
    int c0 = tid * 4;
    int spos0 = g0 & (SS - 1);

    float warr[12];
    #pragma unroll
    for (int i = 0; i < 3; i++) {
        float4 v = *reinterpret_cast<const float4*>(cw + (size_t)c0 * 3 + i * 4);
        warr[i*4+0]=v.x; warr[i*4+1]=v.y; warr[i*4+2]=v.z; warr[i*4+3]=v.w;
    }
    float bv[4];
    {
        float4 v = *reinterpret_cast<const float4*>(cb + c0);
        bv[0]=v.x; bv[1]=v.y; bv[2]=v.z; bv[3]=v.w;
    }

    const float* hbase = g_h + (size_t)g0 * DH + c0;

    float w0r[4], w1r[4], nxt[4];
    {
        float4 vm = (spos0 > 0) ? *reinterpret_cast<const float4*>(hbase - DH)
                                : make_float4(0.f,0.f,0.f,0.f);
        float4 vc = *reinterpret_cast<const float4*>(hbase);
        float4 vn = *reinterpret_cast<const float4*>(hbase + DH);
        w0r[0]=vm.x; w0r[1]=vm.y; w0r[2]=vm.z; w0r[3]=vm.w;
        w1r[0]=vc.x; w1r[1]=vc.y; w1r[2]=vc.z; w1r[3]=vc.w;
        nxt[0]=vn.x; nxt[1]=vn.y; nxt[2]=vn.z; nxt[3]=vn.w;
    }

    float y[4][4];
    float amax[4];
    #pragma unroll
    for (int t = 0; t < 4; t++) {
        float w2r[4];
        #pragma unroll
        for (int j = 0; j < 4; j++) w2r[j] = nxt[j];
        if (t < 3) {
            bool valid = !(t == 2 && spos0 == SS - 4);
            float4 vn = valid ? *reinterpret_cast<const float4*>(hbase + (size_t)(t + 2) * DH)
                              : make_float4(0.f,0.f,0.f,0.f);
            nxt[0]=vn.x; nxt[1]=vn.y; nxt[2]=vn.z; nxt[3]=vn.w;
        }
        float am = 0.0f;
        #pragma unroll
        for (int j = 0; j < 4; j++) {
            float v = bv[j];
            v = fmaf(warr[3*j+0], w0r[j], v);
            v = fmaf(warr[3*j+1], w1r[j], v);
            v = fmaf(warr[3*j+2], w2r[j], v);
            v = v / (1.0f + __expf(-v));      // SiLU (MUFU-based exp)
            y[t][j] = v;
            am = fmaxf(am, fabsf(v));
        }
        amax[t] = am;
        #pragma unroll
        for (int j = 0; j < 4; j++) { w0r[j] = w1r[j]; w1r[j] = w2r[j]; }
    }

    #pragma unroll
    for (int t = 0; t < 4; t++) {
        float v = amax[t];
        #pragma unroll
        for (int o = 16; o > 0; o >>= 1) v = fmaxf(v, __shfl_xor_sync(0xFFFFFFFFu, v, o));
        if ((tid & 31) == 0) sred4[tid >> 5][t] = v;
    }
    __syncthreads();
    if (tid < 128) {
        int w = tid >> 5, lane = tid & 31;
        float v = sred4[lane][w];
        #pragma unroll
        for (int o = 16; o > 0; o >>= 1) v = fmaxf(v, __shfl_xor_sync(0xFFFFFFFFu, v, o));
        if (lane == 0) {
            float s2 = 127.0f / fmaxf(v, 1e-5f);
            s2s[w] = s2;
            g_rowscale2[g0 + w] = 1.0f / s2;
        }
    }
    __syncthreads();

    #pragma unroll
    for (int t = 0; t < 4; t++) {
        float s2 = s2s[t];
        uint2 p;
        p.x = pack_bf16(qr(y[t][0], s2, -128.f, 127.f), qr(y[t][1], s2, -128.f, 127.f));
        p.y = pack_bf16(qr(y[t][2], s2, -128.f, 127.f), qr(y[t][3], s2, -128.f, 127.f));
        *reinterpret_cast<uint2*>(g_q2 + (size_t)(g0 + t) * DH + c0) = p;
    }
}

// ====== bf16 HMMA GEMM: 128x128 block, 128 threads, 64x64 warp tiles ======
// 2 CTAs/SM, 3-stage cp.async, ks-level fragment double-buffering.
// (R12 configuration — known good; do not touch.)
#define BM 128
#define BN 128
#define BK 64                      // 64 bf16 = 128 bytes per smem row
#define STAGES 3
#define TILE_BYTES (128 * 128)     // 16 KB per operand tile
#define STAGE_BYTES (2 * TILE_BYTES)
#define GSMEM_TOTAL (STAGES * STAGE_BYTES)   // 96 KB

__device__ __forceinline__ void cp_async16(uint32_t saddr, const void* g) {
    asm volatile("cp.async.cg.shared.global [%0], [%1], 16;\n" :: "r"(saddr), "l"(g));
}
__device__ __forceinline__ void cp_commit() { asm volatile("cp.async.commit_group;\n"); }
__device__ __forceinline__ void cp_wait1()  { asm volatile("cp.async.wait_group 1;\n"); }

__device__ __forceinline__ void ldm_x4(uint32_t* r, uint32_t saddr) {
    asm volatile("ldmatrix.sync.aligned.m8n8.x4.shared.b16 {%0,%1,%2,%3}, [%4];\n"
        : "=r"(r[0]), "=r"(r[1]), "=r"(r[2]), "=r"(r[3]) : "r"(saddr));
}
__device__ __forceinline__ void mma16816(float* d, const uint32_t* a, const uint32_t* b) {
    asm volatile(
        "mma.sync.aligned.m16n8k16.row.col.f32.bf16.bf16.f32 "
        "{%0,%1,%2,%3},{%4,%5,%6,%7},{%8,%9},{%0,%1,%2,%3};\n"
        : "+f"(d[0]), "+f"(d[1]), "+f"(d[2]), "+f"(d[3])
        : "r"(a[0]), "r"(a[1]), "r"(a[2]), "r"(a[3]), "r"(b[0]), "r"(b[1]));
}

// load one 128x64 A tile + 128x64 B tile with 128 threads (16 cp each)
// 16B-chunk swizzle: phys = ch ^ (row&7)  -> conflict-free ldmatrix + stores
template <int KK>
__device__ __forceinline__ void load_stage(uint32_t sA, uint32_t sB,
                                           const __nv_bfloat16* Ag, const __nv_bfloat16* Bg,
                                           int kElem, int tid) {
    #pragma unroll
    for (int i = 0; i < 8; i++) {          // A: 1024 chunks
        int c = tid + i * 128;
        int row = c >> 3, ch = c & 7;
        int phys = ch ^ (row & 7);
        cp_async16(sA + row * 128 + phys * 16,
                   (const char*)(Ag + (size_t)row * KK + kElem) + ch * 16);
    }
    #pragma unroll
    for (int i = 0; i < 8; i++) {          // B: 1024 chunks
        int c = tid + i * 128;
        int row = c >> 3, ch = c & 7;
        int phys = ch ^ (row & 7);
        cp_async16(sB + row * 128 + phys * 16,
                   (const char*)(Bg + (size_t)row * KK + kElem) + ch * 16);
    }
    cp_commit();
}

// WHICH=0: A=g_xq B=g_wq1 C=g_h   WHICH=1: A=g_q2 B=g_wq2 C=out
template <int WHICH, int NN, int KK>
__global__ void __launch_bounds__(128, 2) gemm_bf16(float* __restrict__ Cout) {
    extern __shared__ __align__(16) char smem[];
    uint32_t s0 = (uint32_t)__cvta_generic_to_shared(smem);

    const __nv_bfloat16* A  = WHICH ? g_q2 : g_xq;
    const __nv_bfloat16* B  = WHICH ? g_wq2 : g_wq1;
    float*               C  = WHICH ? Cout : g_h;
    const float*         rs = WHICH ? g_rowscale2 : g_rowscale1;

    const int tid = threadIdx.x, lane = tid & 31, wid = tid >> 5;
    const int wm = (wid >> 1) * 64, wn = (wid & 1) * 64;   // 2x2 warp grid, 64x64 tiles
    const int m0 = blockIdx.y * BM, n0 = blockIdx.x * BN;

    const __nv_bfloat16* Ag = A + (size_t)m0 * KK;
    const __nv_bfloat16* Bg = B + (size_t)n0 * KK;

    // ldmatrix per-lane base addressing (proven R7 pattern)
    const int rA = wm + (lane & 15);           // + im*16
    const int hiA = lane >> 4;                 // k-half select
    const int xA = rA & 7;
    const int gB = lane >> 3, lrB = lane & 7;
    const int rB = wn + ((gB & 2) << 2) + lrB; // + jp*16
    const int hiB = gB & 1;
    const int xB = rB & 7;

    float acc[4][8][4];
    #pragma unroll
    for (int im = 0; im < 4; im++)
        #pragma unroll
        for (int jn = 0; jn < 8; jn++)
            #pragma unroll
            for (int q = 0; q < 4; q++) acc[im][jn][q] = 0.0f;

    uint32_t af[2][4][4], bf[2][4][4];   // double-buffered fragments

    constexpr int KT = KK / BK;
    #pragma unroll
    for (int p = 0; p < STAGES - 1; p++)
        load_stage<KK>(s0 + p * STAGE_BYTES, s0 + p * STAGE_BYTES + TILE_BYTES,
                       Ag, Bg, p * BK, tid);

    for (int kt = 0; kt < KT; kt++) {
        cp_wait1();                 // stage kt resident
        __syncthreads();            // all warps done with buffer about to be refilled

        const uint32_t sA = s0 + (uint32_t)(kt % STAGES) * STAGE_BYTES;
        const uint32_t sB = sA + TILE_BYTES;
        const uint32_t aL = sA + (uint32_t)rA * 128;
        const uint32_t bL = sB + (uint32_t)rB * 128;

        // ks=0 fragments first (gets LDSM started before the cp.async burst)
        {
            const uint32_t ofA = (uint32_t)((hiA ^ xA) << 4);
            #pragma unroll
            for (int im = 0; im < 4; im++)
                ldm_x4(af[0][im], aL + (uint32_t)(im * 16 * 128) + ofA);
            const uint32_t ofB = (uint32_t)((hiB ^ xB) << 4);
            #pragma unroll
            for (int jp = 0; jp < 4; jp++)
                ldm_x4(bf[0][jp], bL + (uint32_t)(jp * 16 * 128) + ofB);
        }

        // prefetch stage kt+2
        {
            int nk = kt + STAGES - 1;
            if (nk < KT) {
                int pb = nk % STAGES;
                load_stage<KK>(s0 + pb * STAGE_BYTES, s0 + pb * STAGE_BYTES + TILE_BYTES,
                               Ag, Bg, nk * BK, tid);
            } else {
                cp_commit();        // keep group accounting uniform
            }
        }

        #pragma unroll
        for (int ks = 0; ks < 4; ks++) {
            const int cur = ks & 1;
            if (ks < 3) {           // prefetch next k-chunk fragments
                const int nxt = cur ^ 1;
                const uint32_t ofA = (uint32_t)((((ks + 1) * 2 + hiA) ^ xA) << 4);
                #pragma unroll
                for (int im = 0; im < 4; im++)
                    ldm_x4(af[nxt][im], aL + (uint32_t)(im * 16 * 128) + ofA);
                const uint32_t ofB = (uint32_t)((((ks + 1) * 2 + hiB) ^ xB) << 4);
                #pragma unroll
                for (int jp = 0; jp < 4; jp++)
                    ldm_x4(bf[nxt][jp], bL + (uint32_t)(jp * 16 * 128) + ofB);
            }
            #pragma unroll
            for (int im = 0; im < 4; im++)
                #pragma unroll
                for (int jn = 0; jn < 8; jn++)
                    mma16816(acc[im][jn], af[cur][im], &bf[cur][jn >> 1][(jn & 1) * 2]);
        }
    }

    const float ws = g_wscale[WHICH];
    const int g = lane >> 2, t = lane & 3;
    #pragma unroll
    for (int im = 0; im < 4; im++) {
        int r0 = m0 + wm + im * 16 + g;
        float rs0 = rs[r0] * ws;
        float rs1 = rs[r0 + 8] * ws;
        #pragma unroll
        for (int jn = 0; jn < 8; jn++) {
            int cc = n0 + wn + jn * 8 + t * 2;
            float2 v0 = make_float2(acc[im][jn][0] * rs0, acc[im][jn][1] * rs0);
            float2 v1 = make_float2(acc[im][jn][2] * rs1, acc[im][jn][3] * rs1);
            *reinterpret_cast<float2*>(&C[(size_t)r0 * NN + cc]) = v0;
            *reinterpret_cast<float2*>(&C[(size_t)(r0 + 8) * NN + cc]) = v1;
        }
    }
}

// ---------------- launch ----------------
extern "C" void kernel_launch(void* const* d_in, const int* in_sizes, int n_in,
                              void* d_out, int out_size) {
    const float* x  = (const float*)d_in[0];
    const float* w1 = (const float*)d_in[1];
    const float* cw = (const float*)d_in[2];
    const float* cb = (const float*)d_in[3];
    const float* w2 = (const float*)d_in[4];
    float* out = (float*)d_out;
    (void)in_sizes; (void)n_in; (void)out_size;

    static int inited = 0;
    if (!inited) {
        cudaFuncSetAttribute(gemm_bf16<0, DH, DM>, cudaFuncAttributeMaxDynamicSharedMemorySize, GSMEM_TOTAL);
        cudaFuncSetAttribute(gemm_bf16<1, DM, DH>, cudaFuncAttributeMaxDynamicSharedMemorySize, GSMEM_TOTAL);
        inited = 1;
    }

    wsum_all<<<4096, 256>>>(w1, w2);                                            // 1
    quant_all<<<6144, 256>>>(w1, w2, x);                                        // 2
    gemm_bf16<0, DH, DM><<<dim3(DH / BN, MM / BM), 128, GSMEM_TOTAL>>>(nullptr);// 3
    conv_silu_quant4<<<MM / 4, 1024>>>(cw, cb);                                 // 4
    gemm_bf16<1, DM, DH><<<dim3(DM / BN, MM / BM), 128, GSMEM_TOTAL>>>(out);    // 5
}